// round 9
// baseline (speedup 1.0000x reference)
#include <cuda_runtime.h>
#include <cuda_bf16.h>
#include <math.h>
#include <stdint.h>

#define NCTA 128
#define NTH  544               // 16 consumer warps + 1 producer warp
#define B    32
#define TENC 400
#define ED   512
#define TDEC 800
#define DD   80
#define LS   1024
#define UN   128
#define KER  31
#define FIL  32
#define NCH0 13
#define NCH1 16
#define NCHT 29
#define K0REAL 1616
#define ROWE  136              // u16 elems per row (272 B)
#define SROWB 272
#define CHE   (32 * ROWE)      // 4352 elems
#define TILEB 8704
#define STAGEB (4 * TILEB)     // 34816
#define NST   4

// ---- smem offsets (bytes) ----
#define OFF_ZSM   139264       // 8 * 32 * 33 * 4 = 33792
#define OFF_WQS   173056       // 4096
#define OFF_HS    177152       // 1024
#define OFF_MBAR  178176       // 64
#define OFF_AS    178240       // 544
#define OFF_SPART 178784       // 1600
#define OFF_SS    180384       // 1600
#define OFF_AA    181984       // 1600
#define OFF_RED   183584       // 128
#define OFF_RED2  183712       // 8192
#define SMEM_TOTAL 191904

typedef unsigned short u16;

// ---------------- device state ----------------
__device__ __align__(16) u16 g_Wh0[128 * NCH0 * CHE];
__device__ __align__(16) u16 g_Wl0[128 * NCH0 * CHE];
__device__ __align__(16) u16 g_Wh1[128 * NCH1 * CHE];
__device__ __align__(16) u16 g_Wl1[128 * NCH1 * CHE];
__device__ __align__(16) u16 g_x0h[2][NCH0 * CHE];
__device__ __align__(16) u16 g_x0l[2][NCH0 * CHE];
__device__ __align__(16) u16 g_x1h[2][NCH1 * CHE];
__device__ __align__(16) u16 g_x1l[2][NCH1 * CHE];
__device__ __align__(16) u16 g_dech[B * TDEC * DD];
__device__ __align__(16) u16 g_decl[B * TDEC * DD];
__device__ __align__(16) float g_keys[B * TENC * UN];
__device__ float g_c0[B * LS];
__device__ float g_c1[B * LS];
__device__ float g_align[B * TENC];
__device__ float g_scores[B * TENC];
__device__ float g_pq[B * UN];
__device__ float g_Wc[KER * UN];
__device__ float g_locb[UN];
__device__ unsigned g_flag[B];
__device__ unsigned g_bar_count;
__device__ volatile unsigned g_bar_gen;

// ---------------- helpers ----------------
__device__ __forceinline__ void bsplit(float v, u16& h, u16& l) {
    __nv_bfloat16 hb = __float2bfloat16(v);
    float rh = __bfloat162float(hb);
    __nv_bfloat16 lb = __float2bfloat16(v - rh);
    h = *(u16*)&hb; l = *(u16*)&lb;
}
__device__ __forceinline__ void bulk(uint32_t dst, const void* src, uint32_t bytes, uint32_t mb) {
    asm volatile("cp.async.bulk.shared::cta.global.mbarrier::complete_tx::bytes [%0], [%1], %2, [%3];"
                 :: "r"(dst), "l"(src), "r"(bytes), "r"(mb) : "memory");
}
__device__ __forceinline__ void mbar_init(uint32_t mb, uint32_t cnt) {
    asm volatile("mbarrier.init.shared.b64 [%0], %1;" :: "r"(mb), "r"(cnt) : "memory");
}
__device__ __forceinline__ void mbar_expect(uint32_t mb, uint32_t bytes) {
    asm volatile("mbarrier.arrive.expect_tx.shared.b64 _, [%0], %1;" :: "r"(mb), "r"(bytes) : "memory");
}
__device__ __forceinline__ void mbar_arrive(uint32_t mb) {
    asm volatile("mbarrier.arrive.shared.b64 _, [%0];" :: "r"(mb) : "memory");
}
__device__ __forceinline__ void mbar_wait(uint32_t mb, uint32_t phase) {
    asm volatile("{\n\t.reg .pred P;\n"
                 "W%=:\n\tmbarrier.try_wait.parity.shared.b64 P, [%0], %1;\n"
                 "\t@P bra D%=;\n\tbra W%=;\nD%=:\n\t}"
                 :: "r"(mb), "r"(phase) : "memory");
}
__device__ __forceinline__ void ldsm4(uint32_t a, uint32_t& r0, uint32_t& r1,
                                      uint32_t& r2, uint32_t& r3) {
    asm volatile("ldmatrix.sync.aligned.m8n8.x4.shared.b16 {%0,%1,%2,%3}, [%4];"
                 : "=r"(r0), "=r"(r1), "=r"(r2), "=r"(r3) : "r"(a));
}
__device__ __forceinline__ void mma16816(float* c, uint32_t a0, uint32_t a1,
                                         uint32_t a2, uint32_t a3,
                                         uint32_t b0, uint32_t b1) {
    asm volatile("mma.sync.aligned.m16n8k16.row.col.f32.bf16.bf16.f32 "
                 "{%0,%1,%2,%3},{%4,%5,%6,%7},{%8,%9},{%0,%1,%2,%3};"
                 : "+f"(c[0]), "+f"(c[1]), "+f"(c[2]), "+f"(c[3])
                 : "r"(a0), "r"(a1), "r"(a2), "r"(a3), "r"(b0), "r"(b1));
}
__device__ __forceinline__ float fsig(float x) {
    float e = __expf(-x);
    return __fdividef(1.f, 1.f + e);
}
__device__ __forceinline__ float ftanh(float x) {
    x = fminf(15.f, fmaxf(-15.f, x));
    float e = __expf(2.f * x);
    return __fdividef(e - 1.f, e + 1.f);
}

__device__ __forceinline__ void grid_sync() {
    __threadfence();
    __syncthreads();
    if (threadIdx.x == 0) {
        unsigned gen = g_bar_gen;
        if (atomicAdd(&g_bar_count, 1u) == NCTA - 1) {
            g_bar_count = 0;
            __threadfence();
            g_bar_gen = gen + 1;
        } else {
            while (g_bar_gen == gen) __nanosleep(32);
        }
    }
    __syncthreads();
    __threadfence();
}

// ---------------- producer (single thread of warp 16) ----------------
template <int NCH>
__device__ __forceinline__ void produce_phase(uint32_t smbase, int gbase, int cta,
        const u16* Wh, const u16* Wl, const u16* Xh, const u16* Xl) {
    for (int ch = 0; ch < NCH; ch++) {
        int g = gbase + ch, s = g & 3;
        if (g >= NST)
            mbar_wait(smbase + OFF_MBAR + 32 + s * 8, (uint32_t)(((g >> 2) - 1) & 1));
        uint32_t buf = smbase + s * STAGEB;
        uint32_t mb  = smbase + OFF_MBAR + s * 8;
        mbar_expect(mb, 4 * TILEB);
        bulk(buf,             Wh + (size_t)(cta * NCH + ch) * CHE, TILEB, mb);
        bulk(buf + TILEB,     Wl + (size_t)(cta * NCH + ch) * CHE, TILEB, mb);
        bulk(buf + 2 * TILEB, Xh + (size_t)ch * CHE, TILEB, mb);
        bulk(buf + 3 * TILEB, Xl + (size_t)ch * CHE, TILEB, mb);
    }
}

// ---------------- consumer: one phase of chunks ----------------
template <int NCH>
__device__ __forceinline__ void consume_phase(uint32_t smbase, int lane, int gbase,
        uint32_t aoff, uint32_t boff, float c[2][2][4]) {
    for (int ch = 0; ch < NCH; ch++) {
        int g = gbase + ch, s = g & 3;
        mbar_wait(smbase + OFF_MBAR + s * 8, (uint32_t)((g >> 2) & 1));
        uint32_t st = smbase + s * STAGEB;
        uint32_t wh = st, wl = st + TILEB, xh = st + 2 * TILEB, xl = st + 3 * TILEB;
        uint32_t w0, w1, w2, w3, v0, v1, v2, v3;
        ldsm4(wh + boff, w0, w1, w2, w3);
        ldsm4(wl + boff, v0, v1, v2, v3);
        #pragma unroll
        for (int mt = 0; mt < 2; mt++) {
            uint32_t a0, a1, a2, a3, e0, e1, e2, e3;
            ldsm4(xh + aoff + mt * 16 * SROWB, a0, a1, a2, a3);
            ldsm4(xl + aoff + mt * 16 * SROWB, e0, e1, e2, e3);
            mma16816(c[mt][0], a0, a1, a2, a3, w0, w2);
            mma16816(c[mt][0], a0, a1, a2, a3, v0, v2);
            mma16816(c[mt][0], e0, e1, e2, e3, w0, w2);
            mma16816(c[mt][1], a0, a1, a2, a3, w1, w3);
            mma16816(c[mt][1], a0, a1, a2, a3, v1, v3);
            mma16816(c[mt][1], e0, e1, e2, e3, w1, w3);
        }
        if (lane == 0) mbar_arrive(smbase + OFF_MBAR + 32 + s * 8);
    }
}

// ---------------- persistent kernel ----------------
__global__ void __launch_bounds__(NTH, 1) k_persist(
        const float* __restrict__ values, const float* __restrict__ Wq,
        const float* __restrict__ v_a, const float* __restrict__ b_a,
        const float* __restrict__ bias0, const float* __restrict__ bias1,
        float* __restrict__ e_out, float* __restrict__ c_out) {
    extern __shared__ char sm[];
    uint32_t smbase = (uint32_t)__cvta_generic_to_shared(sm);
    int cta = blockIdx.x, tid = threadIdx.x;
    int lane = tid & 31, warp = tid >> 5;
    int nt = warp & 1, kq = warp >> 1, n0 = nt * 16;
    uint32_t aoff = (uint32_t)((lane & 15) * SROWB + (lane >> 4) * 16 + kq * 32);
    uint32_t boff = (uint32_t)((n0 + (lane & 15)) * SROWB + (lane >> 4) * 16 + kq * 32);
    int bb = cta >> 2, qq = cta & 3;
    bool isProd = (warp == 16);

    float* zsm   = (float*)(sm + OFF_ZSM);
    float* wqs   = (float*)(sm + OFF_WQS);
    float* hs    = (float*)(sm + OFF_HS);
    float* aS    = (float*)(sm + OFF_AS);
    float* spart = (float*)(sm + OFF_SPART);
    float* sS    = (float*)(sm + OFF_SS);
    float* aA    = (float*)(sm + OFF_AA);
    float* red   = (float*)(sm + OFF_RED);
    float* red2  = (float*)(sm + OFF_RED2);

    if (tid == 0) {
        #pragma unroll
        for (int s = 0; s < NST; s++) {
            mbar_init(smbase + OFF_MBAR + s * 8, 1);        // full: 1 expect covering 4 bulks
            mbar_init(smbase + OFF_MBAR + 32 + s * 8, 16);  // empty: 16 consumer warps
        }
    }
    // Wq slice (8 rows x 128) into smem
    for (int i = tid; i < 8 * 128; i += NTH)
        wqs[i] = Wq[(size_t)(cta * 8 + (i >> 7)) * UN + (i & 127)];
    __syncthreads();

    for (int t = 0; t < TDEC; t++) {
        int pr = t & 1, cu = pr ^ 1;
        int g0 = NCHT * t, g1 = g0 + NCH0;

        // ---- L0 GEMM ----
        float c[2][2][4];
        #pragma unroll
        for (int a = 0; a < 2; a++)
            #pragma unroll
            for (int bq = 0; bq < 2; bq++)
                #pragma unroll
                for (int j = 0; j < 4; j++) c[a][bq][j] = 0.f;
        if (isProd) {
            if (lane == 0)
                produce_phase<NCH0>(smbase, g0, cta, g_Wh0, g_Wl0, g_x0h[pr], g_x0l[pr]);
        } else {
            consume_phase<NCH0>(smbase, lane, g0, aoff, boff, c);
        }
        // ---- L0 epilogue ----
        if (!isProd) {
            float* zz = zsm + kq * (32 * 33);
            int r = lane >> 2, cp = (lane & 3) * 2;
            #pragma unroll
            for (int mt = 0; mt < 2; mt++)
                #pragma unroll
                for (int nn = 0; nn < 2; nn++) {
                    int col = n0 + nn * 8 + cp;
                    zz[(mt * 16 + r) * 33 + col]         = c[mt][nn][0];
                    zz[(mt * 16 + r) * 33 + col + 1]     = c[mt][nn][1];
                    zz[(mt * 16 + 8 + r) * 33 + col]     = c[mt][nn][2];
                    zz[(mt * 16 + 8 + r) * 33 + col + 1] = c[mt][nn][3];
                }
        }
        __syncthreads();
        if (tid < 256) {
            int j = tid >> 5, b = tid & 31;
            int u = cta * 8 + j;
            float z[4];
            #pragma unroll
            for (int g4 = 0; g4 < 4; g4++) {
                float v = bias0[g4 * 1024 + u];
                #pragma unroll
                for (int q = 0; q < 8; q++) v += zsm[q * 1056 + b * 33 + g4 * 8 + j];
                z[g4] = v;
            }
            float co = g_c0[b * LS + u];
            float cn = fsig(z[1]) * co + fsig(z[0]) * ftanh(z[2]);
            g_c0[b * LS + u] = cn;
            float h = fsig(z[3]) * ftanh(cn);
            u16 hh, ll; bsplit(h, hh, ll);
            size_t o1 = ((size_t)(u >> 7) * 32 + b) * ROWE + (u & 127);        // x1 k=u
            g_x1h[pr][o1] = hh; g_x1l[pr][o1] = ll;
            int k0 = 592 + u;
            size_t o0 = ((size_t)(k0 >> 7) * 32 + b) * ROWE + (k0 & 127);      // x0 next step
            g_x0h[cu][o0] = hh; g_x0l[cu][o0] = ll;
        }
        grid_sync();

        // ---- L1 GEMM ----
        #pragma unroll
        for (int a = 0; a < 2; a++)
            #pragma unroll
            for (int bq = 0; bq < 2; bq++)
                #pragma unroll
                for (int j = 0; j < 4; j++) c[a][bq][j] = 0.f;
        if (isProd) {
            if (lane == 0)
                produce_phase<NCH1>(smbase, g1, cta, g_Wh1, g_Wl1, g_x1h[pr], g_x1l[pr]);
        } else {
            consume_phase<NCH1>(smbase, lane, g1, aoff, boff, c);
        }
        // ---- L1 epilogue (+ fused pq partial) ----
        if (!isProd) {
            float* zz = zsm + kq * (32 * 33);
            int r = lane >> 2, cp = (lane & 3) * 2;
            #pragma unroll
            for (int mt = 0; mt < 2; mt++)
                #pragma unroll
                for (int nn = 0; nn < 2; nn++) {
                    int col = n0 + nn * 8 + cp;
                    zz[(mt * 16 + r) * 33 + col]         = c[mt][nn][0];
                    zz[(mt * 16 + r) * 33 + col + 1]     = c[mt][nn][1];
                    zz[(mt * 16 + 8 + r) * 33 + col]     = c[mt][nn][2];
                    zz[(mt * 16 + 8 + r) * 33 + col + 1] = c[mt][nn][3];
                }
        }
        __syncthreads();
        if (tid < 256) {
            int j = tid >> 5, b = tid & 31;
            int u = cta * 8 + j;
            float z[4];
            #pragma unroll
            for (int g4 = 0; g4 < 4; g4++) {
                float v = bias1[g4 * 1024 + u];
                #pragma unroll
                for (int q = 0; q < 8; q++) v += zsm[q * 1056 + b * 33 + g4 * 8 + j];
                z[g4] = v;
            }
            float co = g_c1[b * LS + u];
            float cn = fsig(z[1]) * co + fsig(z[0]) * ftanh(z[2]);
            g_c1[b * LS + u] = cn;
            float h = fsig(z[3]) * ftanh(cn);
            u16 hh, ll; bsplit(h, hh, ll);
            int k1 = 1024 + u;
            size_t o1 = ((size_t)(k1 >> 7) * 32 + b) * ROWE + (k1 & 127);
            g_x1h[cu][o1] = hh; g_x1l[cu][o1] = ll;
            hs[j * 32 + b] = h;
        }
        __syncthreads();
        if (tid < 512) {   // pq partial: rank-8 update, RED.ADD to g_pq
            int b = tid >> 4, u0 = (tid & 15) * 8;
            float acc[8] = {0.f, 0.f, 0.f, 0.f, 0.f, 0.f, 0.f, 0.f};
            #pragma unroll
            for (int jj = 0; jj < 8; jj++) {
                float h = hs[jj * 32 + b];
                #pragma unroll
                for (int q = 0; q < 8; q++) acc[q] += h * wqs[jj * 128 + u0 + q];
            }
            #pragma unroll
            for (int q = 0; q < 8; q++) atomicAdd(&g_pq[b * UN + u0 + q], acc[q]);
        }
        grid_sync();

        // ---- P3: location conv + scores ----
        {
            int t0 = qq * 100;
            int u = tid & 127, q4 = tid >> 7;
            for (int i = tid; i < 130; i += NTH) {
                int tg = t0 - 15 + i;
                aS[i] = (tg >= 0 && tg < TENC) ? __ldcg(&g_align[bb * TENC + tg]) : 0.f;
            }
            float pqu = __ldg(&b_a[u]) + __ldg(&g_locb[u]) + __ldcg(&g_pq[bb * UN + u]);
            float vau = __ldg(&v_a[u]);
            float wc[KER];
            #pragma unroll
            for (int k = 0; k < KER; k++) wc[k] = __ldg(&g_Wc[k * UN + u]);
            __syncthreads();
            if (tid < 512) {
                int wq = warp & 3;
                for (int tt = 0; tt < 25; tt++) {
                    int tl = q4 * 25 + tt;
                    float s = __ldg(&g_keys[((size_t)bb * TENC + t0 + tl) * UN + u]) + pqu;
                    #pragma unroll
                    for (int k = 0; k < KER; k++) s += aS[tl + k] * wc[k];
                    float r = vau * ftanh(s);
                    #pragma unroll
                    for (int o = 16; o; o >>= 1) r += __shfl_xor_sync(0xffffffffu, r, o);
                    if (lane == 0) spart[tl * 4 + wq] = r;
                }
            }
            __syncthreads();
            if (tid < 100)
                g_scores[bb * TENC + t0 + tid] =
                    spart[tid * 4] + spart[tid * 4 + 1] + spart[tid * 4 + 2] + spart[tid * 4 + 3];
            __threadfence();
            __syncthreads();
            if (tid == 0) atomicAdd(&g_flag[bb], 1u);
        }

        // ---- P4: softmax + outputs + context slice ----
        {
            if (tid == 0) {
                unsigned tg = 4u * (unsigned)(t + 1);
                while (*((volatile unsigned*)&g_flag[bb]) < tg) __nanosleep(32);
            }
            __syncthreads();
            __threadfence();
            float lm = -1e30f;
            if (tid < TENC) { lm = __ldcg(&g_scores[bb * TENC + tid]); sS[tid] = lm; }
            #pragma unroll
            for (int o = 16; o; o >>= 1) lm = fmaxf(lm, __shfl_xor_sync(0xffffffffu, lm, o));
            if (lane == 0 && warp < 16) red[warp] = lm;
            __syncthreads();
            float m = red[0];
            #pragma unroll
            for (int w = 1; w < 16; w++) m = fmaxf(m, red[w]);
            float ex = (tid < TENC) ? __expf(sS[tid] - m) : 0.f;
            float ls = ex;
            #pragma unroll
            for (int o = 16; o; o >>= 1) ls += __shfl_xor_sync(0xffffffffu, ls, o);
            if (lane == 0 && warp < 16) red[16 + warp] = ls;
            __syncthreads();
            float S = 0.f;
            #pragma unroll
            for (int w = 0; w < 16; w++) S += red[16 + w];
            float inv = __fdividef(1.f, S);
            if (tid < TENC) aA[tid] = ex * inv;
            __syncthreads();
            if (qq == 0 && tid < TENC) {
                float a = aA[tid];
                e_out[((size_t)bb * TDEC + t) * TENC + tid] = a;
                float al = __ldcg(&g_align[bb * TENC + tid]) + a;
                __stcg(&g_align[bb * TENC + tid], al);
            }
            // dec prefetch for next step (chunk 0, row bb, k = 0..79)
            if (qq == 1 && t + 1 < TDEC && tid < DD) {
                size_t sidx = ((size_t)bb * TDEC + (t + 1)) * DD + tid;
                size_t xo = (size_t)bb * ROWE + tid;
                g_x0h[cu][xo] = g_dech[sidx];
                g_x0l[cu][xo] = g_decl[sidx];
            }
            if (qq == 3 && tid < UN) __stcg(&g_pq[bb * UN + tid], 0.f);
            // context slice [qq*128, +128): 16 warps x 25 rows
            if (warp < 16) {
                int g16 = warp;
                float4 acc = make_float4(0.f, 0.f, 0.f, 0.f);
                const float* vp = values + ((size_t)bb * TENC + g16 * 25) * ED + qq * 128 + lane * 4;
                #pragma unroll 5
                for (int r = 0; r < 25; r++) {
                    float a = aA[g16 * 25 + r];
                    float4 v = *(const float4*)(vp + (size_t)r * ED);
                    acc.x += a * v.x; acc.y += a * v.y;
                    acc.z += a * v.z; acc.w += a * v.w;
                }
                ((float4*)red2)[g16 * 32 + lane] = acc;
            }
            __syncthreads();
            if (tid < 128) {
                float s = 0.f;
                #pragma unroll
                for (int gg = 0; gg < 16; gg++) s += red2[gg * 128 + tid];
                int d = qq * 128 + tid;
                c_out[((size_t)bb * TDEC + t) * ED + d] = s;
                int kk = 80 + d;
                u16 hh, ll; bsplit(s, hh, ll);
                size_t xo = ((size_t)(kk >> 7) * 32 + bb) * ROWE + (kk & 127);
                g_x0h[cu][xo] = hh; g_x0l[cu][xo] = ll;
            }
        }
        grid_sync();
    }
}

// ---------------- prep kernels ----------------
__global__ void k_prep(const float* __restrict__ dec, const float* __restrict__ ck,
                       const float* __restrict__ cb, const float* __restrict__ Wloc) {
    int gid = blockIdx.x * 256 + threadIdx.x;
    int stride = gridDim.x * 256;
    for (int i = gid; i < KER * UN; i += stride) {
        int k = i >> 7, u = i & 127;
        float s = 0.f;
        for (int f = 0; f < FIL; f++) s += ck[k * FIL + f] * Wloc[f * UN + u];
        g_Wc[i] = s;
    }
    for (int i = gid; i < UN; i += stride) {
        float s = 0.f;
        for (int f = 0; f < FIL; f++) s += cb[f] * Wloc[f * UN + i];
        g_locb[i] = s;
    }
    for (int i = gid; i < B * LS; i += stride) { g_c0[i] = 0.f; g_c1[i] = 0.f; }
    for (int i = gid; i < B * TENC; i += stride) g_align[i] = 0.f;
    for (int i = gid; i < B * UN; i += stride) g_pq[i] = 0.f;
    for (int i = gid; i < B; i += stride) g_flag[i] = 0u;
    if (gid == 0) { g_bar_count = 0u; g_bar_gen = 0u; }
    for (int i = gid; i < 2 * NCH0 * CHE; i += stride) {
        int par = i / (NCH0 * CHE), r = i % (NCH0 * CHE);
        int ch = r / CHE, rr = r % CHE;
        int b = rr / ROWE, kk = rr % ROWE;
        float v = 0.f;
        if (par == 0 && ch == 0 && kk < DD) v = dec[(size_t)b * TDEC * DD + kk];
        u16 hh, ll; bsplit(v, hh, ll);
        g_x0h[par][r] = hh; g_x0l[par][r] = ll;
    }
    for (int i = gid; i < 2 * NCH1 * CHE; i += stride) {
        int par = i / (NCH1 * CHE), r = i % (NCH1 * CHE);
        g_x1h[par][r] = 0; g_x1l[par][r] = 0;
    }
    for (size_t i = gid; i < (size_t)B * TDEC * DD; i += stride) {
        u16 hh, ll; bsplit(dec[i], hh, ll);
        g_dech[i] = hh; g_decl[i] = ll;
    }
}

__global__ void k_wt(const float* __restrict__ W0, const float* __restrict__ U0,
                     const float* __restrict__ W1, const float* __restrict__ U1) {
    size_t idx = (size_t)blockIdx.x * 256 + threadIdx.x;
    const size_t total0 = (size_t)128 * NCH0 * CHE;
    const size_t total1 = (size_t)128 * NCH1 * CHE;
    int layer; size_t li;
    const float *W, *U; int ksplit, kreal, nch;
    if (idx < total0) {
        layer = 0; li = idx; W = W0; U = U0; ksplit = DD + ED; kreal = K0REAL; nch = NCH0;
    } else if (idx < total0 + total1) {
        layer = 1; li = idx - total0; W = W1; U = U1; ksplit = LS; kreal = 2 * LS; nch = NCH1;
    } else return;
    int kk = (int)(li % ROWE);
    size_t t1 = li / ROWE;
    int n = (int)(t1 & 31);
    size_t t2 = t1 >> 5;
    int ch = (int)(t2 % nch);
    int cta = (int)(t2 / nch);
    float v = 0.f;
    if (kk < 128) {
        int k = ch * 128 + kk;
        int col = (n >> 3) * 1024 + cta * 8 + (n & 7);
        if (k < ksplit)      v = W[(size_t)k * 4096 + col];
        else if (k < kreal)  v = U[(size_t)(k - ksplit) * 4096 + col];
    }
    u16 hh, ll; bsplit(v, hh, ll);
    if (layer == 0) { g_Wh0[li] = hh; g_Wl0[li] = ll; }
    else            { g_Wh1[li] = hh; g_Wl1[li] = ll; }
}

__global__ void k_keys(const float* __restrict__ values, const float* __restrict__ Wm) {
    int b = blockIdx.x, t0 = blockIdx.y * 50;
    __shared__ float vs[10][ED];
    int u = threadIdx.x;
    for (int g = 0; g < 5; g++) {
        int tb = t0 + g * 10;
        __syncthreads();
        for (int i = u; i < 10 * ED; i += 128) {
            int tt = i >> 9, d = i & 511;
            vs[tt][d] = values[((size_t)b * TENC + tb + tt) * ED + d];
        }
        __syncthreads();
        float acc[10];
        #pragma unroll
        for (int tt = 0; tt < 10; tt++) acc[tt] = 0.f;
        for (int d = 0; d < ED; d++) {
            float w = Wm[d * UN + u];
            #pragma unroll
            for (int tt = 0; tt < 10; tt++) acc[tt] += vs[tt][d] * w;
        }
        #pragma unroll
        for (int tt = 0; tt < 10; tt++)
            g_keys[((size_t)b * TENC + tb + tt) * UN + u] = acc[tt];
    }
}

// ---------------- launch ----------------
extern "C" void kernel_launch(void* const* d_in, const int* in_sizes, int n_in,
                              void* d_out, int out_size) {
    const float* values = (const float*)d_in[0];
    const float* dec    = (const float*)d_in[1];
    const float* Wm     = (const float*)d_in[2];
    const float* Wq     = (const float*)d_in[3];
    const float* convk  = (const float*)d_in[4];
    const float* convb  = (const float*)d_in[5];
    const float* Wloc   = (const float*)d_in[6];
    const float* v_a    = (const float*)d_in[7];
    const float* b_a    = (const float*)d_in[8];
    const float* W0     = (const float*)d_in[9];
    const float* U0     = (const float*)d_in[10];
    const float* b0     = (const float*)d_in[11];
    const float* W1     = (const float*)d_in[12];
    const float* U1     = (const float*)d_in[13];
    const float* b1     = (const float*)d_in[14];

    float* out   = (float*)d_out;
    float* c_out = out;                              // [B, TDEC, ED]
    float* e_out = out + (size_t)B * TDEC * ED;      // [B, TDEC, TENC]

    static int smem_set = 0;
    if (!smem_set) {
        cudaFuncSetAttribute(k_persist, cudaFuncAttributeMaxDynamicSharedMemorySize, SMEM_TOTAL);
        smem_set = 1;
    }

    size_t totalw = (size_t)128 * (NCH0 + NCH1) * CHE;
    k_prep<<<512, 256>>>(dec, convk, convb, Wloc);
    k_wt<<<(unsigned)((totalw + 255) / 256), 256>>>(W0, U0, W1, U1);
    k_keys<<<dim3(B, 8), 128>>>(values, Wm);

    k_persist<<<NCTA, NTH, SMEM_TOTAL>>>(values, Wq, v_a, b_a, b0, b1, e_out, c_out);
}

// round 11
// speedup vs baseline: 1.1243x; 1.1243x over previous
#include <cuda_runtime.h>
#include <cuda_bf16.h>
#include <math.h>
#include <stdint.h>

#define NCTA 128
#define B    32
#define TENC 400
#define ED   512
#define TDEC 800
#define DD   80
#define LS   1024
#define UN   128
#define KER  31
#define FIL  32
#define NCH0 13
#define NCH1 16
#define NCHT 29
#define K0REAL 1616
#define ROWE  136              // u16 elems per row (272 B)
#define SROWB 272
#define CHE   (32 * ROWE)      // 4352 elems
#define TILEB 8704
#define STAGEB (4 * TILEB)     // 34816
#define NST   4

// ---- smem offsets (bytes) ----
#define OFF_ZSM   139264
#define OFF_KEYS  156160
#define OFF_WQS   207360
#define OFF_HS    211456
#define OFF_MBAR  212480
#define OFF_AS    212560
#define OFF_SPART 213104
#define OFF_SS    214704
#define OFF_AA    216304
#define OFF_RED   217904
#define OFF_RED2  218032
#define SMEM_TOTAL 226224

typedef unsigned short u16;

// ---------------- device state ----------------
__device__ __align__(16) u16 g_Wh0[128 * NCH0 * CHE];
__device__ __align__(16) u16 g_Wl0[128 * NCH0 * CHE];
__device__ __align__(16) u16 g_Wh1[128 * NCH1 * CHE];
__device__ __align__(16) u16 g_Wl1[128 * NCH1 * CHE];
__device__ __align__(16) u16 g_x0h[2][NCH0 * CHE];
__device__ __align__(16) u16 g_x0l[2][NCH0 * CHE];
__device__ __align__(16) u16 g_x1h[2][NCH1 * CHE];
__device__ __align__(16) u16 g_x1l[2][NCH1 * CHE];
__device__ __align__(16) u16 g_dech[B * TDEC * DD];
__device__ __align__(16) u16 g_decl[B * TDEC * DD];
__device__ __align__(16) float g_keys[B * TENC * UN];
__device__ float g_c0[B * LS];
__device__ float g_c1[B * LS];
__device__ float g_align[B * TENC];
__device__ float g_scores[B * TENC];
__device__ float g_pq[B * UN];
__device__ float g_Wc[KER * UN];
__device__ float g_locb[UN];
__device__ unsigned g_flag[B];
__device__ unsigned g_bar_count;
__device__ volatile unsigned g_bar_gen;

// ---------------- helpers ----------------
__device__ __forceinline__ void bsplit(float v, u16& h, u16& l) {
    __nv_bfloat16 hb = __float2bfloat16(v);
    float rh = __bfloat162float(hb);
    __nv_bfloat16 lb = __float2bfloat16(v - rh);
    h = *(u16*)&hb; l = *(u16*)&lb;
}
__device__ __forceinline__ void bulk(uint32_t dst, const void* src, uint32_t bytes, uint32_t mb) {
    asm volatile("cp.async.bulk.shared::cta.global.mbarrier::complete_tx::bytes [%0], [%1], %2, [%3];"
                 :: "r"(dst), "l"(src), "r"(bytes), "r"(mb) : "memory");
}
__device__ __forceinline__ void mbar_init(uint32_t mb, uint32_t cnt) {
    asm volatile("mbarrier.init.shared.b64 [%0], %1;" :: "r"(mb), "r"(cnt) : "memory");
}
__device__ __forceinline__ void mbar_expect(uint32_t mb, uint32_t bytes) {
    asm volatile("mbarrier.arrive.expect_tx.shared.b64 _, [%0], %1;" :: "r"(mb), "r"(bytes) : "memory");
}
__device__ __forceinline__ void mbar_arrive(uint32_t mb) {
    asm volatile("mbarrier.arrive.shared.b64 _, [%0];" :: "r"(mb) : "memory");
}
__device__ __forceinline__ void mbar_wait(uint32_t mb, uint32_t phase) {
    asm volatile("{\n\t.reg .pred P;\n"
                 "W%=:\n\tmbarrier.try_wait.parity.shared.b64 P, [%0], %1;\n"
                 "\t@P bra D%=;\n\tbra W%=;\nD%=:\n\t}"
                 :: "r"(mb), "r"(phase) : "memory");
}
__device__ __forceinline__ void ldsm4(uint32_t a, uint32_t& r0, uint32_t& r1,
                                      uint32_t& r2, uint32_t& r3) {
    asm volatile("ldmatrix.sync.aligned.m8n8.x4.shared.b16 {%0,%1,%2,%3}, [%4];"
                 : "=r"(r0), "=r"(r1), "=r"(r2), "=r"(r3) : "r"(a));
}
__device__ __forceinline__ void ldsm2(uint32_t a, uint32_t& r0, uint32_t& r1) {
    asm volatile("ldmatrix.sync.aligned.m8n8.x2.shared.b16 {%0,%1}, [%2];"
                 : "=r"(r0), "=r"(r1) : "r"(a));
}
__device__ __forceinline__ void mma16816(float* c, uint32_t a0, uint32_t a1,
                                         uint32_t a2, uint32_t a3,
                                         uint32_t b0, uint32_t b1) {
    asm volatile("mma.sync.aligned.m16n8k16.row.col.f32.bf16.bf16.f32 "
                 "{%0,%1,%2,%3},{%4,%5,%6,%7},{%8,%9},{%0,%1,%2,%3};"
                 : "+f"(c[0]), "+f"(c[1]), "+f"(c[2]), "+f"(c[3])
                 : "r"(a0), "r"(a1), "r"(a2), "r"(a3), "r"(b0), "r"(b1));
}
// fast transcendentals (MUFU-based) — the ONLY change vs the round-7 kernel
__device__ __forceinline__ float fsig(float x) {
    float e = __expf(-x);
    return __fdividef(1.f, 1.f + e);
}
__device__ __forceinline__ float ftanh(float x) {
    x = fminf(15.f, fmaxf(-15.f, x));
    float e = __expf(2.f * x);
    return __fdividef(e - 1.f, e + 1.f);
}

__device__ __forceinline__ void grid_sync() {
    __threadfence();
    __syncthreads();
    if (threadIdx.x == 0) {
        unsigned gen = g_bar_gen;
        if (atomicAdd(&g_bar_count, 1u) == NCTA - 1) {
            g_bar_count = 0;
            __threadfence();
            g_bar_gen = gen + 1;
        } else {
            while (g_bar_gen == gen) __nanosleep(32);
        }
    }
    __syncthreads();
    __threadfence();
}

// ---------------- issue helpers (tid 0 only) ----------------
__device__ __forceinline__ void issueW(uint32_t smbase, int g,
                                       const u16* Wh, const u16* Wl, size_t chunkIdx) {
    int s = g & 3;
    if (g >= NST) mbar_wait(smbase + OFF_MBAR + 32 + s * 8, (uint32_t)(((g >> 2) - 1) & 1));
    uint32_t buf = smbase + s * STAGEB;
    uint32_t mb  = smbase + OFF_MBAR + s * 8;
    mbar_expect(mb, 2 * TILEB);
    bulk(buf,         Wh + chunkIdx * CHE, TILEB, mb);
    bulk(buf + TILEB, Wl + chunkIdx * CHE, TILEB, mb);
}
__device__ __forceinline__ void issueX(uint32_t smbase, int g,
                                       const u16* Xh, const u16* Xl, int ch) {
    int s = g & 3;
    uint32_t buf = smbase + s * STAGEB;
    uint32_t mb  = smbase + OFF_MBAR + s * 8;
    mbar_expect(mb, 2 * TILEB);
    bulk(buf + 2 * TILEB, Xh + (size_t)ch * CHE, TILEB, mb);
    bulk(buf + 3 * TILEB, Xl + (size_t)ch * CHE, TILEB, mb);
}

// ---------------- chunk MMA (per warp: 32-k quarter of a 128-k chunk) ----------------
__device__ __forceinline__ void chunk_mma(uint32_t st, uint32_t aoff, uint32_t boff,
                                          float* c0a, float* c1a) {
    uint32_t wh = st, wl = st + TILEB, xh = st + 2 * TILEB, xl = st + 3 * TILEB;
    #pragma unroll
    for (int kk = 0; kk < 2; kk++) {
        uint32_t kb = kk * 32;
        uint32_t b0, b1, f0, f1;
        ldsm2(wh + boff + kb, b0, b1);
        ldsm2(wl + boff + kb, f0, f1);
        uint32_t a0, a1, a2, a3, e0, e1, e2, e3;
        ldsm4(xh + aoff + kb, a0, a1, a2, a3);
        ldsm4(xl + aoff + kb, e0, e1, e2, e3);
        mma16816(c0a, a0, a1, a2, a3, b0, b1);
        mma16816(c0a, a0, a1, a2, a3, f0, f1);
        mma16816(c0a, e0, e1, e2, e3, b0, b1);
        ldsm4(xh + aoff + kb + 16 * SROWB, a0, a1, a2, a3);
        ldsm4(xl + aoff + kb + 16 * SROWB, e0, e1, e2, e3);
        mma16816(c1a, a0, a1, a2, a3, b0, b1);
        mma16816(c1a, a0, a1, a2, a3, f0, f1);
        mma16816(c1a, e0, e1, e2, e3, b0, b1);
    }
}

template <int NCH>
__device__ __forceinline__ void gemm_phase(uint32_t smbase, int tid, int lane, int gbase, int cta,
        const u16* Wh, const u16* Wl, const u16* Xh, const u16* Xl,
        uint32_t aoff, uint32_t boff, float* c0a, float* c1a) {
    for (int ch = 0; ch < NCH; ch++) {
        int g = gbase + ch;
        int s = g & 3;
        mbar_wait(smbase + OFF_MBAR + s * 8, (uint32_t)((g >> 2) & 1));
        chunk_mma(smbase + s * STAGEB, aoff, boff, c0a, c1a);
        if (lane == 0) mbar_arrive(smbase + OFF_MBAR + 32 + s * 8);
        if (tid == 0 && ch + NST < NCH) {
            issueW(smbase, g + NST, Wh, Wl, (size_t)(cta * NCH + ch + NST));
            issueX(smbase, g + NST, Xh, Xl, ch + NST);
        }
    }
}

// ---------------- persistent kernel ----------------
__global__ void __launch_bounds__(512, 1) k_persist(
        const float* __restrict__ values, const float* __restrict__ Wq,
        const float* __restrict__ v_a, const float* __restrict__ b_a,
        const float* __restrict__ bias0, const float* __restrict__ bias1,
        float* __restrict__ e_out, float* __restrict__ c_out) {
    extern __shared__ char sm[];
    uint32_t smbase = (uint32_t)__cvta_generic_to_shared(sm);
    int cta = blockIdx.x, tid = threadIdx.x;
    int lane = tid & 31, warp = tid >> 5;
    int nt = warp & 3, kh = warp >> 2, n0 = nt * 8;
    uint32_t aoff = (uint32_t)((lane & 15) * SROWB + (lane >> 4) * 16 + kh * 64);
    uint32_t boff = (uint32_t)((n0 + (lane & 7)) * SROWB + ((lane >> 3) & 1) * 16 + kh * 64);
    int bb = cta >> 2, qq = cta & 3;

    float* zsm   = (float*)(sm + OFF_ZSM);
    float* keysS = (float*)(sm + OFF_KEYS);
    float* wqs   = (float*)(sm + OFF_WQS);
    float* hs    = (float*)(sm + OFF_HS);
    float* aS    = (float*)(sm + OFF_AS);
    float* spart = (float*)(sm + OFF_SPART);
    float* sS    = (float*)(sm + OFF_SS);
    float* aA    = (float*)(sm + OFF_AA);
    float* red   = (float*)(sm + OFF_RED);
    float* red2  = (float*)(sm + OFF_RED2);

    if (tid == 0) {
        #pragma unroll
        for (int s = 0; s < NST; s++) {
            mbar_init(smbase + OFF_MBAR + s * 8, 2);        // full (2 expect_tx arrivals)
            mbar_init(smbase + OFF_MBAR + 32 + s * 8, 16);  // empty (16 warps)
        }
        mbar_init(smbase + OFF_MBAR + 64, 1);               // keys
    }
    // Wq slice (8 rows x 128) into smem
    for (int i = tid; i < 8 * 128; i += 512)
        wqs[i] = Wq[(size_t)(cta * 8 + (i >> 7)) * UN + (i & 127)];
    __syncthreads();
    if (tid == 0) {
        // keys tile (step-invariant): one 51.2 KB bulk
        uint32_t km = smbase + OFF_MBAR + 64;
        mbar_expect(km, 100 * UN * 4);
        bulk(smbase + OFF_KEYS, g_keys + ((size_t)bb * TENC + qq * 100) * UN, 100 * UN * 4, km);
        // prologue: chunks 0..3 of L0(t=0)
        #pragma unroll
        for (int i = 0; i < NST; i++) {
            issueW(smbase, i, g_Wh0, g_Wl0, (size_t)(cta * NCH0 + i));
            issueX(smbase, i, g_x0h[0], g_x0l[0], i);
        }
    }
    mbar_wait(smbase + OFF_MBAR + 64, 0);   // all threads: keys resident
    __syncthreads();

    for (int t = 0; t < TDEC; t++) {
        int pr = t & 1, cu = pr ^ 1;
        int g0 = NCHT * t, g1 = g0 + NCH0;

        // X for L0 chunks 0..3 (W pre-issued in previous L1 epilogue; t=0 in prologue)
        if (tid == 0 && t > 0) {
            #pragma unroll
            for (int i = 0; i < NST; i++) issueX(smbase, g0 + i, g_x0h[pr], g_x0l[pr], i);
        }
        float c0a[4] = {0.f, 0.f, 0.f, 0.f}, c1a[4] = {0.f, 0.f, 0.f, 0.f};
        gemm_phase<NCH0>(smbase, tid, lane, g0, cta, g_Wh0, g_Wl0, g_x0h[pr], g_x0l[pr],
                         aoff, boff, c0a, c1a);
        // ---- L0 epilogue ----
        {
            float* zz = zsm + kh * (32 * 33);
            int r = lane >> 2, cp = (lane & 3) * 2;
            zz[r * 33 + n0 + cp]            = c0a[0];
            zz[r * 33 + n0 + cp + 1]        = c0a[1];
            zz[(r + 8) * 33 + n0 + cp]      = c0a[2];
            zz[(r + 8) * 33 + n0 + cp + 1]  = c0a[3];
            zz[(16 + r) * 33 + n0 + cp]     = c1a[0];
            zz[(16 + r) * 33 + n0 + cp + 1] = c1a[1];
            zz[(24 + r) * 33 + n0 + cp]     = c1a[2];
            zz[(24 + r) * 33 + n0 + cp + 1] = c1a[3];
            __syncthreads();
            if (tid == 0) {   // pre-issue W for first 4 L1 chunks
                #pragma unroll
                for (int i = 0; i < NST; i++)
                    issueW(smbase, g1 + i, g_Wh1, g_Wl1, (size_t)(cta * NCH1 + i));
            }
            if (tid < 256) {
                int j = tid >> 5, b = tid & 31;
                int u = cta * 8 + j;
                float z[4];
                #pragma unroll
                for (int g4 = 0; g4 < 4; g4++) {
                    float v = bias0[g4 * 1024 + u];
                    #pragma unroll
                    for (int q = 0; q < 4; q++) v += zsm[q * 1056 + b * 33 + g4 * 8 + j];
                    z[g4] = v;
                }
                float co = g_c0[b * LS + u];
                float cn = fsig(z[1]) * co + fsig(z[0]) * ftanh(z[2]);
                g_c0[b * LS + u] = cn;
                float h = fsig(z[3]) * ftanh(cn);
                u16 hh, ll; bsplit(h, hh, ll);
                size_t o1 = ((size_t)(u >> 7) * 32 + b) * ROWE + (u & 127);          // x1 k=u
                g_x1h[pr][o1] = hh; g_x1l[pr][o1] = ll;
                int k0 = 592 + u;
                size_t o0 = ((size_t)(k0 >> 7) * 32 + b) * ROWE + (k0 & 127);        // x0 next
                g_x0h[cu][o0] = hh; g_x0l[cu][o0] = ll;
            }
        }
        grid_sync();

        if (tid == 0) {
            #pragma unroll
            for (int i = 0; i < NST; i++) issueX(smbase, g1 + i, g_x1h[pr], g_x1l[pr], i);
        }
        #pragma unroll
        for (int j = 0; j < 4; j++) { c0a[j] = 0.f; c1a[j] = 0.f; }
        gemm_phase<NCH1>(smbase, tid, lane, g1, cta, g_Wh1, g_Wl1, g_x1h[pr], g_x1l[pr],
                         aoff, boff, c0a, c1a);
        // ---- L1 epilogue (+ fused pq partial) ----
        {
            float* zz = zsm + kh * (32 * 33);
            int r = lane >> 2, cp = (lane & 3) * 2;
            zz[r * 33 + n0 + cp]            = c0a[0];
            zz[r * 33 + n0 + cp + 1]        = c0a[1];
            zz[(r + 8) * 33 + n0 + cp]      = c0a[2];
            zz[(r + 8) * 33 + n0 + cp + 1]  = c0a[3];
            zz[(16 + r) * 33 + n0 + cp]     = c1a[0];
            zz[(16 + r) * 33 + n0 + cp + 1] = c1a[1];
            zz[(24 + r) * 33 + n0 + cp]     = c1a[2];
            zz[(24 + r) * 33 + n0 + cp + 1] = c1a[3];
            __syncthreads();
            if (tid == 0 && t + 1 < TDEC) {   // pre-issue W for next step's L0
                #pragma unroll
                for (int i = 0; i < NST; i++)
                    issueW(smbase, NCHT * (t + 1) + i, g_Wh0, g_Wl0, (size_t)(cta * NCH0 + i));
            }
            if (tid < 256) {
                int j = tid >> 5, b = tid & 31;
                int u = cta * 8 + j;
                float z[4];
                #pragma unroll
                for (int g4 = 0; g4 < 4; g4++) {
                    float v = bias1[g4 * 1024 + u];
                    #pragma unroll
                    for (int q = 0; q < 4; q++) v += zsm[q * 1056 + b * 33 + g4 * 8 + j];
                    z[g4] = v;
                }
                float co = g_c1[b * LS + u];
                float cn = fsig(z[1]) * co + fsig(z[0]) * ftanh(z[2]);
                g_c1[b * LS + u] = cn;
                float h = fsig(z[3]) * ftanh(cn);
                u16 hh, ll; bsplit(h, hh, ll);
                int k1 = 1024 + u;
                size_t o1 = ((size_t)(k1 >> 7) * 32 + b) * ROWE + (k1 & 127);
                g_x1h[cu][o1] = hh; g_x1l[cu][o1] = ll;
                hs[j * 32 + b] = h;
            }
            __syncthreads();
            // pq partial: rank-8 update, RED.ADD to g_pq
            {
                int b = tid >> 4, u0 = (tid & 15) * 8;
                float acc[8] = {0.f, 0.f, 0.f, 0.f, 0.f, 0.f, 0.f, 0.f};
                #pragma unroll
                for (int jj = 0; jj < 8; jj++) {
                    float h = hs[jj * 32 + b];
                    #pragma unroll
                    for (int q = 0; q < 8; q++) acc[q] += h * wqs[jj * 128 + u0 + q];
                }
                #pragma unroll
                for (int q = 0; q < 8; q++) atomicAdd(&g_pq[b * UN + u0 + q], acc[q]);
            }
        }
        grid_sync();

        // ---- P3: location conv + scores (keys & Wc smem/reg resident) ----
        {
            int t0 = qq * 100;
            int u = tid & 127, q4 = tid >> 7;
            for (int i = tid; i < 130; i += 512) {
                int tg = t0 - 15 + i;
                aS[i] = (tg >= 0 && tg < TENC) ? __ldcg(&g_align[bb * TENC + tg]) : 0.f;
            }
            float pqu = __ldg(&b_a[u]) + __ldg(&g_locb[u]) + __ldcg(&g_pq[bb * UN + u]);
            float vau = __ldg(&v_a[u]);
            float wc[KER];
            #pragma unroll
            for (int k = 0; k < KER; k++) wc[k] = __ldg(&g_Wc[k * UN + u]);
            __syncthreads();
            int wq = warp & 3;
            for (int tt = 0; tt < 25; tt++) {
                int tl = q4 * 25 + tt;
                float s = keysS[tl * 128 + u] + pqu;
                #pragma unroll
                for (int k = 0; k < KER; k++) s += aS[tl + k] * wc[k];
                float r = vau * ftanh(s);
                #pragma unroll
                for (int o = 16; o; o >>= 1) r += __shfl_xor_sync(0xffffffffu, r, o);
                if (lane == 0) spart[tl * 4 + wq] = r;
            }
            __syncthreads();
            if (tid < 100)
                g_scores[bb * TENC + t0 + tid] =
                    spart[tid * 4] + spart[tid * 4 + 1] + spart[tid * 4 + 2] + spart[tid * 4 + 3];
            __threadfence();
            __syncthreads();
            if (tid == 0) atomicAdd(&g_flag[bb], 1u);
        }

        // ---- P4: softmax + outputs + context slice ----
        {
            if (tid == 0) {
                unsigned tg = 4u * (unsigned)(t + 1);
                while (*((volatile unsigned*)&g_flag[bb]) < tg) __nanosleep(32);
            }
            __syncthreads();
            __threadfence();
            float lm = -1e30f;
            if (tid < TENC) { lm = __ldcg(&g_scores[bb * TENC + tid]); sS[tid] = lm; }
            #pragma unroll
            for (int o = 16; o; o >>= 1) lm = fmaxf(lm, __shfl_xor_sync(0xffffffffu, lm, o));
            if (lane == 0) red[warp] = lm;
            __syncthreads();
            float m = red[0];
            #pragma unroll
            for (int w = 1; w < 16; w++) m = fmaxf(m, red[w]);
            float ex = (tid < TENC) ? __expf(sS[tid] - m) : 0.f;
            float ls = ex;
            #pragma unroll
            for (int o = 16; o; o >>= 1) ls += __shfl_xor_sync(0xffffffffu, ls, o);
            if (lane == 0) red[16 + warp] = ls;
            __syncthreads();
            float S = 0.f;
            #pragma unroll
            for (int w = 0; w < 16; w++) S += red[16 + w];
            float inv = __fdividef(1.f, S);
            if (tid < TENC) aA[tid] = ex * inv;
            __syncthreads();
            if (qq == 0 && tid < TENC) {
                float a = aA[tid];
                e_out[((size_t)bb * TDEC + t) * TENC + tid] = a;
                float al = __ldcg(&g_align[bb * TENC + tid]) + a;
                __stcg(&g_align[bb * TENC + tid], al);
            }
            // dec prefetch for next step (chunk 0, row bb, k = 0..79)
            if (qq == 1 && t + 1 < TDEC && tid < DD) {
                size_t sidx = ((size_t)bb * TDEC + (t + 1)) * DD + tid;
                size_t xo = (size_t)bb * ROWE + tid;
                g_x0h[cu][xo] = g_dech[sidx];
                g_x0l[cu][xo] = g_decl[sidx];
            }
            if (qq == 3 && tid < UN) __stcg(&g_pq[bb * UN + tid], 0.f);
            // context slice [qq*128, +128): 16 warps x 25 rows
            int g16 = tid >> 5;
            float4 acc = make_float4(0.f, 0.f, 0.f, 0.f);
            const float* vp = values + ((size_t)bb * TENC + g16 * 25) * ED + qq * 128 + lane * 4;
            #pragma unroll 5
            for (int r = 0; r < 25; r++) {
                float a = aA[g16 * 25 + r];
                float4 v = *(const float4*)(vp + (size_t)r * ED);
                acc.x += a * v.x; acc.y += a * v.y;
                acc.z += a * v.z; acc.w += a * v.w;
            }
            ((float4*)red2)[g16 * 32 + lane] = acc;
            __syncthreads();
            if (tid < 128) {
                float s = 0.f;
                #pragma unroll
                for (int gg = 0; gg < 16; gg++) s += red2[gg * 128 + tid];
                int d = qq * 128 + tid;
                c_out[((size_t)bb * TDEC + t) * ED + d] = s;
                int kk = 80 + d;
                u16 hh, ll; bsplit(s, hh, ll);
                size_t xo = ((size_t)(kk >> 7) * 32 + bb) * ROWE + (kk & 127);
                g_x0h[cu][xo] = hh; g_x0l[cu][xo] = ll;
            }
        }
        grid_sync();
    }
}

// ---------------- prep kernels ----------------
__global__ void k_prep(const float* __restrict__ dec, const float* __restrict__ ck,
                       const float* __restrict__ cb, const float* __restrict__ Wloc) {
    int gid = blockIdx.x * 256 + threadIdx.x;
    int stride = gridDim.x * 256;
    for (int i = gid; i < KER * UN; i += stride) {
        int k = i >> 7, u = i & 127;
        float s = 0.f;
        for (int f = 0; f < FIL; f++) s += ck[k * FIL + f] * Wloc[f * UN + u];
        g_Wc[i] = s;
    }
    for (int i = gid; i < UN; i += stride) {
        float s = 0.f;
        for (int f = 0; f < FIL; f++) s += cb[f] * Wloc[f * UN + i];
        g_locb[i] = s;
    }
    for (int i = gid; i < B * LS; i += stride) { g_c0[i] = 0.f; g_c1[i] = 0.f; }
    for (int i = gid; i < B * TENC; i += stride) g_align[i] = 0.f;
    for (int i = gid; i < B * UN; i += stride) g_pq[i] = 0.f;
    for (int i = gid; i < B; i += stride) g_flag[i] = 0u;
    if (gid == 0) { g_bar_count = 0u; g_bar_gen = 0u; }
    for (int i = gid; i < 2 * NCH0 * CHE; i += stride) {
        int par = i / (NCH0 * CHE), r = i % (NCH0 * CHE);
        int ch = r / CHE, rr = r % CHE;
        int b = rr / ROWE, kk = rr % ROWE;
        float v = 0.f;
        if (par == 0 && ch == 0 && kk < DD) v = dec[(size_t)b * TDEC * DD + kk];
        u16 hh, ll; bsplit(v, hh, ll);
        g_x0h[par][r] = hh; g_x0l[par][r] = ll;
    }
    for (int i = gid; i < 2 * NCH1 * CHE; i += stride) {
        int par = i / (NCH1 * CHE), r = i % (NCH1 * CHE);
        g_x1h[par][r] = 0; g_x1l[par][r] = 0;
    }
    for (size_t i = gid; i < (size_t)B * TDEC * DD; i += stride) {
        u16 hh, ll; bsplit(dec[i], hh, ll);
        g_dech[i] = hh; g_decl[i] = ll;
    }
}

__global__ void k_wt(const float* __restrict__ W0, const float* __restrict__ U0,
                     const float* __restrict__ W1, const float* __restrict__ U1) {
    size_t idx = (size_t)blockIdx.x * 256 + threadIdx.x;
    const size_t total0 = (size_t)128 * NCH0 * CHE;
    const size_t total1 = (size_t)128 * NCH1 * CHE;
    int layer; size_t li;
    const float *W, *U; int ksplit, kreal, nch;
    if (idx < total0) {
        layer = 0; li = idx; W = W0; U = U0; ksplit = DD + ED; kreal = K0REAL; nch = NCH0;
    } else if (idx < total0 + total1) {
        layer = 1; li = idx - total0; W = W1; U = U1; ksplit = LS; kreal = 2 * LS; nch = NCH1;
    } else return;
    int kk = (int)(li % ROWE);
    size_t t1 = li / ROWE;
    int n = (int)(t1 & 31);
    size_t t2 = t1 >> 5;
    int ch = (int)(t2 % nch);
    int cta = (int)(t2 / nch);
    float v = 0.f;
    if (kk < 128) {
        int k = ch * 128 + kk;
        int col = (n >> 3) * 1024 + cta * 8 + (n & 7);
        if (k < ksplit)      v = W[(size_t)k * 4096 + col];
        else if (k < kreal)  v = U[(size_t)(k - ksplit) * 4096 + col];
    }
    u16 hh, ll; bsplit(v, hh, ll);
    if (layer == 0) { g_Wh0[li] = hh; g_Wl0[li] = ll; }
    else            { g_Wh1[li] = hh; g_Wl1[li] = ll; }
}

__global__ void k_keys(const float* __restrict__ values, const float* __restrict__ Wm) {
    int b = blockIdx.x, t0 = blockIdx.y * 50;
    __shared__ float vs[10][ED];
    int u = threadIdx.x;
    for (int g = 0; g < 5; g++) {
        int tb = t0 + g * 10;
        __syncthreads();
        for (int i = u; i < 10 * ED; i += 128) {
            int tt = i >> 9, d = i & 511;
            vs[tt][d] = values[((size_t)b * TENC + tb + tt) * ED + d];
        }
        __syncthreads();
        float acc[10];
        #pragma unroll
        for (int tt = 0; tt < 10; tt++) acc[tt] = 0.f;
        for (int d = 0; d < ED; d++) {
            float w = Wm[d * UN + u];
            #pragma unroll
            for (int tt = 0; tt < 10; tt++) acc[tt] += vs[tt][d] * w;
        }
        #pragma unroll
        for (int tt = 0; tt < 10; tt++)
            g_keys[((size_t)b * TENC + tb + tt) * UN + u] = acc[tt];
    }
}

// ---------------- launch ----------------
extern "C" void kernel_launch(void* const* d_in, const int* in_sizes, int n_in,
                              void* d_out, int out_size) {
    const float* values = (const float*)d_in[0];
    const float* dec    = (const float*)d_in[1];
    const float* Wm     = (const float*)d_in[2];
    const float* Wq     = (const float*)d_in[3];
    const float* convk  = (const float*)d_in[4];
    const float* convb  = (const float*)d_in[5];
    const float* Wloc   = (const float*)d_in[6];
    const float* v_a    = (const float*)d_in[7];
    const float* b_a    = (const float*)d_in[8];
    const float* W0     = (const float*)d_in[9];
    const float* U0     = (const float*)d_in[10];
    const float* b0     = (const float*)d_in[11];
    const float* W1     = (const float*)d_in[12];
    const float* U1     = (const float*)d_in[13];
    const float* b1     = (const float*)d_in[14];

    float* out   = (float*)d_out;
    float* c_out = out;                              // [B, TDEC, ED]
    float* e_out = out + (size_t)B * TDEC * ED;      // [B, TDEC, TENC]

    static int smem_set = 0;
    if (!smem_set) {
        cudaFuncSetAttribute(k_persist, cudaFuncAttributeMaxDynamicSharedMemorySize, SMEM_TOTAL);
        smem_set = 1;
    }

    size_t totalw = (size_t)128 * (NCH0 + NCH1) * CHE;
    k_prep<<<512, 256>>>(dec, convk, convb, Wloc);
    k_wt<<<(unsigned)((totalw + 255) / 256), 256>>>(W0, U0, W1, U1);
    k_keys<<<dim3(B, 8), 128>>>(values, Wm);

    k_persist<<<NCTA, 512, SMEM_TOTAL>>>(values, Wq, v_a, b_a, b0, b1, e_out, c_out);
}

// round 12
// speedup vs baseline: 1.1267x; 1.0021x over previous
#include <cuda_runtime.h>
#include <cuda_bf16.h>
#include <math.h>
#include <stdint.h>

#define NCTA 128
#define B    32
#define TENC 400
#define ED   512
#define TDEC 800
#define DD   80
#define LS   1024
#define UN   128
#define KER  31
#define FIL  32
#define NCH0 13
#define NCH1 16
#define NCHT 29
#define K0REAL 1616
#define ROWE  136              // u16 elems per row (272 B)
#define SROWB 272
#define CHE   (32 * ROWE)      // 4352 elems
#define TILEB 8704
#define STAGEB (4 * TILEB)     // 34816
#define NST   4

// ---- smem offsets (bytes) ----
#define OFF_ZSM   139264
#define OFF_KEYS  156160
#define OFF_WQS   207360
#define OFF_HS    211456
#define OFF_MBAR  212480
#define OFF_AS    212560
#define OFF_SPART 213104
#define OFF_SS    214704
#define OFF_AA    216304
#define OFF_RED   217904
#define OFF_RED2  218032
#define SMEM_TOTAL 226224

typedef unsigned short u16;

// ---------------- device state ----------------
__device__ __align__(16) u16 g_Wh0[128 * NCH0 * CHE];
__device__ __align__(16) u16 g_Wl0[128 * NCH0 * CHE];
__device__ __align__(16) u16 g_Wh1[128 * NCH1 * CHE];
__device__ __align__(16) u16 g_Wl1[128 * NCH1 * CHE];
__device__ __align__(16) u16 g_x0h[2][NCH0 * CHE];
__device__ __align__(16) u16 g_x0l[2][NCH0 * CHE];
__device__ __align__(16) u16 g_x1h[2][NCH1 * CHE];
__device__ __align__(16) u16 g_x1l[2][NCH1 * CHE];
__device__ __align__(16) u16 g_dech[B * TDEC * DD];
__device__ __align__(16) u16 g_decl[B * TDEC * DD];
__device__ __align__(16) float g_keys[B * TENC * UN];
__device__ float g_c0[B * LS];
__device__ float g_c1[B * LS];
__device__ float g_align[B * TENC];
__device__ float g_scores[B * TENC];
__device__ float g_pq[B * UN];
__device__ float g_Wc[KER * UN];
__device__ float g_locb[UN];
__device__ unsigned g_flag[B];
__device__ unsigned g_bar_count;
__device__ volatile unsigned g_bar_gen;

// ---------------- helpers ----------------
__device__ __forceinline__ void bsplit(float v, u16& h, u16& l) {
    __nv_bfloat16 hb = __float2bfloat16(v);
    float rh = __bfloat162float(hb);
    __nv_bfloat16 lb = __float2bfloat16(v - rh);
    h = *(u16*)&hb; l = *(u16*)&lb;
}
__device__ __forceinline__ void bulk(uint32_t dst, const void* src, uint32_t bytes, uint32_t mb) {
    asm volatile("cp.async.bulk.shared::cta.global.mbarrier::complete_tx::bytes [%0], [%1], %2, [%3];"
                 :: "r"(dst), "l"(src), "r"(bytes), "r"(mb) : "memory");
}
__device__ __forceinline__ void mbar_init(uint32_t mb, uint32_t cnt) {
    asm volatile("mbarrier.init.shared.b64 [%0], %1;" :: "r"(mb), "r"(cnt) : "memory");
}
__device__ __forceinline__ void mbar_expect(uint32_t mb, uint32_t bytes) {
    asm volatile("mbarrier.arrive.expect_tx.shared.b64 _, [%0], %1;" :: "r"(mb), "r"(bytes) : "memory");
}
__device__ __forceinline__ void mbar_arrive(uint32_t mb) {
    asm volatile("mbarrier.arrive.shared.b64 _, [%0];" :: "r"(mb) : "memory");
}
__device__ __forceinline__ void mbar_wait(uint32_t mb, uint32_t phase) {
    asm volatile("{\n\t.reg .pred P;\n"
                 "W%=:\n\tmbarrier.try_wait.parity.shared.b64 P, [%0], %1;\n"
                 "\t@P bra D%=;\n\tbra W%=;\nD%=:\n\t}"
                 :: "r"(mb), "r"(phase) : "memory");
}
__device__ __forceinline__ void ldsm4(uint32_t a, uint32_t& r0, uint32_t& r1,
                                      uint32_t& r2, uint32_t& r3) {
    asm volatile("ldmatrix.sync.aligned.m8n8.x4.shared.b16 {%0,%1,%2,%3}, [%4];"
                 : "=r"(r0), "=r"(r1), "=r"(r2), "=r"(r3) : "r"(a));
}
__device__ __forceinline__ void mma16816(float* c, uint32_t a0, uint32_t a1,
                                         uint32_t a2, uint32_t a3,
                                         uint32_t b0, uint32_t b1) {
    asm volatile("mma.sync.aligned.m16n8k16.row.col.f32.bf16.bf16.f32 "
                 "{%0,%1,%2,%3},{%4,%5,%6,%7},{%8,%9},{%0,%1,%2,%3};"
                 : "+f"(c[0]), "+f"(c[1]), "+f"(c[2]), "+f"(c[3])
                 : "r"(a0), "r"(a1), "r"(a2), "r"(a3), "r"(b0), "r"(b1));
}
// fast transcendentals (MUFU-based)
__device__ __forceinline__ float fsig(float x) {
    float e = __expf(-x);
    return __fdividef(1.f, 1.f + e);
}
__device__ __forceinline__ float ftanh(float x) {
    x = fminf(15.f, fmaxf(-15.f, x));
    float e = __expf(2.f * x);
    return __fdividef(e - 1.f, e + 1.f);
}

__device__ __forceinline__ void grid_sync() {
    __threadfence();
    __syncthreads();
    if (threadIdx.x == 0) {
        unsigned gen = g_bar_gen;
        if (atomicAdd(&g_bar_count, 1u) == NCTA - 1) {
            g_bar_count = 0;
            __threadfence();
            g_bar_gen = gen + 1;
        } else {
            while (g_bar_gen == gen) __nanosleep(32);
        }
    }
    __syncthreads();
    __threadfence();
}

// ---------------- issue helpers (tid 0 only) ----------------
__device__ __forceinline__ void issueW(uint32_t smbase, int g,
                                       const u16* Wh, const u16* Wl, size_t chunkIdx) {
    int s = g & 3;
    if (g >= NST) mbar_wait(smbase + OFF_MBAR + 32 + s * 8, (uint32_t)(((g >> 2) - 1) & 1));
    uint32_t buf = smbase + s * STAGEB;
    uint32_t mb  = smbase + OFF_MBAR + s * 8;
    mbar_expect(mb, 2 * TILEB);
    bulk(buf,         Wh + chunkIdx * CHE, TILEB, mb);
    bulk(buf + TILEB, Wl + chunkIdx * CHE, TILEB, mb);
}
__device__ __forceinline__ void issueX(uint32_t smbase, int g,
                                       const u16* Xh, const u16* Xl, int ch) {
    int s = g & 3;
    uint32_t buf = smbase + s * STAGEB;
    uint32_t mb  = smbase + OFF_MBAR + s * 8;
    mbar_expect(mb, 2 * TILEB);
    bulk(buf + 2 * TILEB, Xh + (size_t)ch * CHE, TILEB, mb);
    bulk(buf + 3 * TILEB, Xl + (size_t)ch * CHE, TILEB, mb);
}

// ---------------- chunk MMA (2n x 8k retile: warp covers 16 n-cols x 16 k) ----------------
__device__ __forceinline__ void chunk_mma(uint32_t st, uint32_t aoff, uint32_t boff,
                                          float c[2][2][4]) {
    uint32_t wh = st, wl = st + TILEB, xh = st + 2 * TILEB, xl = st + 3 * TILEB;
    uint32_t w0, w1, w2, w3, v0, v1, v2, v3;
    ldsm4(wh + boff, w0, w1, w2, w3);
    ldsm4(wl + boff, v0, v1, v2, v3);
    #pragma unroll
    for (int mt = 0; mt < 2; mt++) {
        uint32_t a0, a1, a2, a3, e0, e1, e2, e3;
        ldsm4(xh + aoff + mt * 16 * SROWB, a0, a1, a2, a3);
        ldsm4(xl + aoff + mt * 16 * SROWB, e0, e1, e2, e3);
        mma16816(c[mt][0], a0, a1, a2, a3, w0, w2);
        mma16816(c[mt][0], a0, a1, a2, a3, v0, v2);
        mma16816(c[mt][0], e0, e1, e2, e3, w0, w2);
        mma16816(c[mt][1], a0, a1, a2, a3, w1, w3);
        mma16816(c[mt][1], a0, a1, a2, a3, v1, v3);
        mma16816(c[mt][1], e0, e1, e2, e3, w1, w3);
    }
}

template <int NCH>
__device__ __forceinline__ void gemm_phase(uint32_t smbase, int tid, int lane, int gbase, int cta,
        const u16* Wh, const u16* Wl, const u16* Xh, const u16* Xl,
        uint32_t aoff, uint32_t boff, float c[2][2][4]) {
    for (int ch = 0; ch < NCH; ch++) {
        int g = gbase + ch;
        int s = g & 3;
        mbar_wait(smbase + OFF_MBAR + s * 8, (uint32_t)((g >> 2) & 1));
        chunk_mma(smbase + s * STAGEB, aoff, boff, c);
        if (lane == 0) mbar_arrive(smbase + OFF_MBAR + 32 + s * 8);
        if (tid == 0 && ch + NST < NCH) {
            issueW(smbase, g + NST, Wh, Wl, (size_t)(cta * NCH + ch + NST));
            issueX(smbase, g + NST, Xh, Xl, ch + NST);
        }
    }
}

// two-pass partial store: warps kq<4 store into region (kq&3); kq>=4 accumulate
__device__ __forceinline__ void zstore(float* zsm, int kq, int n0, int lane,
                                       float c[2][2][4]) {
    float* zz = zsm + (kq & 3) * 1056;
    int r = lane >> 2, cp = (lane & 3) * 2;
    if (kq < 4) {
        #pragma unroll
        for (int mt = 0; mt < 2; mt++)
            #pragma unroll
            for (int nn = 0; nn < 2; nn++) {
                int col = n0 + nn * 8 + cp;
                zz[(mt * 16 + r) * 33 + col]         = c[mt][nn][0];
                zz[(mt * 16 + r) * 33 + col + 1]     = c[mt][nn][1];
                zz[(mt * 16 + 8 + r) * 33 + col]     = c[mt][nn][2];
                zz[(mt * 16 + 8 + r) * 33 + col + 1] = c[mt][nn][3];
            }
    }
    __syncthreads();
    if (kq >= 4) {
        #pragma unroll
        for (int mt = 0; mt < 2; mt++)
            #pragma unroll
            for (int nn = 0; nn < 2; nn++) {
                int col = n0 + nn * 8 + cp;
                zz[(mt * 16 + r) * 33 + col]         += c[mt][nn][0];
                zz[(mt * 16 + r) * 33 + col + 1]     += c[mt][nn][1];
                zz[(mt * 16 + 8 + r) * 33 + col]     += c[mt][nn][2];
                zz[(mt * 16 + 8 + r) * 33 + col + 1] += c[mt][nn][3];
            }
    }
    __syncthreads();
}

// ---------------- persistent kernel ----------------
__global__ void __launch_bounds__(512, 1) k_persist(
        const float* __restrict__ values, const float* __restrict__ Wq,
        const float* __restrict__ v_a, const float* __restrict__ b_a,
        const float* __restrict__ bias0, const float* __restrict__ bias1,
        float* __restrict__ e_out, float* __restrict__ c_out) {
    extern __shared__ char sm[];
    uint32_t smbase = (uint32_t)__cvta_generic_to_shared(sm);
    int cta = blockIdx.x, tid = threadIdx.x;
    int lane = tid & 31, warp = tid >> 5;
    int nt = warp & 1, kq = warp >> 1, n0 = nt * 16;
    uint32_t aoff = (uint32_t)((lane & 15) * SROWB + (lane >> 4) * 16 + kq * 32);
    uint32_t boff = (uint32_t)((n0 + (lane & 15)) * SROWB + (lane >> 4) * 16 + kq * 32);
    int bb = cta >> 2, qq = cta & 3;

    float* zsm   = (float*)(sm + OFF_ZSM);
    float* keysS = (float*)(sm + OFF_KEYS);
    float* wqs   = (float*)(sm + OFF_WQS);
    float* hs    = (float*)(sm + OFF_HS);
    float* aS    = (float*)(sm + OFF_AS);
    float* spart = (float*)(sm + OFF_SPART);
    float* sS    = (float*)(sm + OFF_SS);
    float* aA    = (float*)(sm + OFF_AA);
    float* red   = (float*)(sm + OFF_RED);
    float* red2  = (float*)(sm + OFF_RED2);

    if (tid == 0) {
        #pragma unroll
        for (int s = 0; s < NST; s++) {
            mbar_init(smbase + OFF_MBAR + s * 8, 2);        // full (2 expect_tx arrivals)
            mbar_init(smbase + OFF_MBAR + 32 + s * 8, 16);  // empty (16 warps)
        }
        mbar_init(smbase + OFF_MBAR + 64, 1);               // keys
    }
    // Wq slice (8 rows x 128) into smem
    for (int i = tid; i < 8 * 128; i += 512)
        wqs[i] = Wq[(size_t)(cta * 8 + (i >> 7)) * UN + (i & 127)];
    __syncthreads();
    if (tid == 0) {
        uint32_t km = smbase + OFF_MBAR + 64;
        mbar_expect(km, 100 * UN * 4);
        bulk(smbase + OFF_KEYS, g_keys + ((size_t)bb * TENC + qq * 100) * UN, 100 * UN * 4, km);
        #pragma unroll
        for (int i = 0; i < NST; i++) {
            issueW(smbase, i, g_Wh0, g_Wl0, (size_t)(cta * NCH0 + i));
            issueX(smbase, i, g_x0h[0], g_x0l[0], i);
        }
    }
    mbar_wait(smbase + OFF_MBAR + 64, 0);
    __syncthreads();

    for (int t = 0; t < TDEC; t++) {
        int pr = t & 1, cu = pr ^ 1;
        int g0 = NCHT * t, g1 = g0 + NCH0;

        // X for L0 chunks 0..3 (W pre-issued in previous L1 epilogue; t=0 in prologue)
        if (tid == 0 && t > 0) {
            #pragma unroll
            for (int i = 0; i < NST; i++) issueX(smbase, g0 + i, g_x0h[pr], g_x0l[pr], i);
        }
        float c[2][2][4];
        #pragma unroll
        for (int a = 0; a < 2; a++)
            #pragma unroll
            for (int bq = 0; bq < 2; bq++)
                #pragma unroll
                for (int j = 0; j < 4; j++) c[a][bq][j] = 0.f;
        gemm_phase<NCH0>(smbase, tid, lane, g0, cta, g_Wh0, g_Wl0, g_x0h[pr], g_x0l[pr],
                         aoff, boff, c);
        // ---- L0 epilogue ----
        zstore(zsm, kq, n0, lane, c);
        if (tid == 0) {   // pre-issue W for first 4 L1 chunks
            #pragma unroll
            for (int i = 0; i < NST; i++)
                issueW(smbase, g1 + i, g_Wh1, g_Wl1, (size_t)(cta * NCH1 + i));
        }
        if (tid < 256) {
            int j = tid >> 5, b = tid & 31;
            int u = cta * 8 + j;
            float z[4];
            #pragma unroll
            for (int g4 = 0; g4 < 4; g4++) {
                float v = bias0[g4 * 1024 + u];
                #pragma unroll
                for (int q = 0; q < 4; q++) v += zsm[q * 1056 + b * 33 + g4 * 8 + j];
                z[g4] = v;
            }
            float co = g_c0[b * LS + u];
            float cn = fsig(z[1]) * co + fsig(z[0]) * ftanh(z[2]);
            g_c0[b * LS + u] = cn;
            float h = fsig(z[3]) * ftanh(cn);
            u16 hh, ll; bsplit(h, hh, ll);
            size_t o1 = ((size_t)(u >> 7) * 32 + b) * ROWE + (u & 127);          // x1 k=u
            g_x1h[pr][o1] = hh; g_x1l[pr][o1] = ll;
            int k0 = 592 + u;
            size_t o0 = ((size_t)(k0 >> 7) * 32 + b) * ROWE + (k0 & 127);        // x0 next
            g_x0h[cu][o0] = hh; g_x0l[cu][o0] = ll;
        }
        grid_sync();

        if (tid == 0) {
            #pragma unroll
            for (int i = 0; i < NST; i++) issueX(smbase, g1 + i, g_x1h[pr], g_x1l[pr], i);
        }
        #pragma unroll
        for (int a = 0; a < 2; a++)
            #pragma unroll
            for (int bq = 0; bq < 2; bq++)
                #pragma unroll
                for (int j = 0; j < 4; j++) c[a][bq][j] = 0.f;
        gemm_phase<NCH1>(smbase, tid, lane, g1, cta, g_Wh1, g_Wl1, g_x1h[pr], g_x1l[pr],
                         aoff, boff, c);
        // ---- L1 epilogue (+ fused pq partial) ----
        zstore(zsm, kq, n0, lane, c);
        if (tid == 0 && t + 1 < TDEC) {   // pre-issue W for next step's L0
            #pragma unroll
            for (int i = 0; i < NST; i++)
                issueW(smbase, NCHT * (t + 1) + i, g_Wh0, g_Wl0, (size_t)(cta * NCH0 + i));
        }
        if (tid < 256) {
            int j = tid >> 5, b = tid & 31;
            int u = cta * 8 + j;
            float z[4];
            #pragma unroll
            for (int g4 = 0; g4 < 4; g4++) {
                float v = bias1[g4 * 1024 + u];
                #pragma unroll
                for (int q = 0; q < 4; q++) v += zsm[q * 1056 + b * 33 + g4 * 8 + j];
                z[g4] = v;
            }
            float co = g_c1[b * LS + u];
            float cn = fsig(z[1]) * co + fsig(z[0]) * ftanh(z[2]);
            g_c1[b * LS + u] = cn;
            float h = fsig(z[3]) * ftanh(cn);
            u16 hh, ll; bsplit(h, hh, ll);
            int k1 = 1024 + u;
            size_t o1 = ((size_t)(k1 >> 7) * 32 + b) * ROWE + (k1 & 127);
            g_x1h[cu][o1] = hh; g_x1l[cu][o1] = ll;
            hs[j * 32 + b] = h;
        }
        __syncthreads();
        // pq partial: rank-8 update, RED.ADD to g_pq
        {
            int b = tid >> 4, u0 = (tid & 15) * 8;
            float acc[8] = {0.f, 0.f, 0.f, 0.f, 0.f, 0.f, 0.f, 0.f};
            #pragma unroll
            for (int jj = 0; jj < 8; jj++) {
                float h = hs[jj * 32 + b];
                #pragma unroll
                for (int q = 0; q < 8; q++) acc[q] += h * wqs[jj * 128 + u0 + q];
            }
            #pragma unroll
            for (int q = 0; q < 8; q++) atomicAdd(&g_pq[b * UN + u0 + q], acc[q]);
        }
        grid_sync();

        // ---- P3: location conv + scores (keys & Wc smem/reg resident) ----
        {
            int t0 = qq * 100;
            int u = tid & 127, q4 = tid >> 7;
            for (int i = tid; i < 130; i += 512) {
                int tg = t0 - 15 + i;
                aS[i] = (tg >= 0 && tg < TENC) ? __ldcg(&g_align[bb * TENC + tg]) : 0.f;
            }
            float pqu = __ldg(&b_a[u]) + __ldg(&g_locb[u]) + __ldcg(&g_pq[bb * UN + u]);
            float vau = __ldg(&v_a[u]);
            float wc[KER];
            #pragma unroll
            for (int k = 0; k < KER; k++) wc[k] = __ldg(&g_Wc[k * UN + u]);
            __syncthreads();
            int wq = warp & 3;
            for (int tt = 0; tt < 25; tt++) {
                int tl = q4 * 25 + tt;
                float s = keysS[tl * 128 + u] + pqu;
                #pragma unroll
                for (int k = 0; k < KER; k++) s += aS[tl + k] * wc[k];
                float r = vau * ftanh(s);
                #pragma unroll
                for (int o = 16; o; o >>= 1) r += __shfl_xor_sync(0xffffffffu, r, o);
                if (lane == 0) spart[tl * 4 + wq] = r;
            }
            __syncthreads();
            if (tid < 100)
                g_scores[bb * TENC + t0 + tid] =
                    spart[tid * 4] + spart[tid * 4 + 1] + spart[tid * 4 + 2] + spart[tid * 4 + 3];
            __threadfence();
            __syncthreads();
            if (tid == 0) atomicAdd(&g_flag[bb], 1u);
        }

        // ---- P4: softmax + outputs + context slice ----
        {
            if (tid == 0) {
                unsigned tg = 4u * (unsigned)(t + 1);
                while (*((volatile unsigned*)&g_flag[bb]) < tg) __nanosleep(32);
            }
            __syncthreads();
            __threadfence();
            float lm = -1e30f;
            if (tid < TENC) { lm = __ldcg(&g_scores[bb * TENC + tid]); sS[tid] = lm; }
            #pragma unroll
            for (int o = 16; o; o >>= 1) lm = fmaxf(lm, __shfl_xor_sync(0xffffffffu, lm, o));
            if (lane == 0) red[warp] = lm;
            __syncthreads();
            float m = red[0];
            #pragma unroll
            for (int w = 1; w < 16; w++) m = fmaxf(m, red[w]);
            float ex = (tid < TENC) ? __expf(sS[tid] - m) : 0.f;
            float ls = ex;
            #pragma unroll
            for (int o = 16; o; o >>= 1) ls += __shfl_xor_sync(0xffffffffu, ls, o);
            if (lane == 0) red[16 + warp] = ls;
            __syncthreads();
            float S = 0.f;
            #pragma unroll
            for (int w = 0; w < 16; w++) S += red[16 + w];
            float inv = __fdividef(1.f, S);
            if (tid < TENC) aA[tid] = ex * inv;
            __syncthreads();
            if (qq == 0 && tid < TENC) {
                float a = aA[tid];
                e_out[((size_t)bb * TDEC + t) * TENC + tid] = a;
                float al = __ldcg(&g_align[bb * TENC + tid]) + a;
                __stcg(&g_align[bb * TENC + tid], al);
            }
            // dec prefetch for next step (chunk 0, row bb, k = 0..79)
            if (qq == 1 && t + 1 < TDEC && tid < DD) {
                size_t sidx = ((size_t)bb * TDEC + (t + 1)) * DD + tid;
                size_t xo = (size_t)bb * ROWE + tid;
                g_x0h[cu][xo] = g_dech[sidx];
                g_x0l[cu][xo] = g_decl[sidx];
            }
            if (qq == 3 && tid < UN) __stcg(&g_pq[bb * UN + tid], 0.f);
            // context slice [qq*128, +128): 16 warps x 25 rows
            int g16 = tid >> 5;
            float4 acc = make_float4(0.f, 0.f, 0.f, 0.f);
            const float* vp = values + ((size_t)bb * TENC + g16 * 25) * ED + qq * 128 + lane * 4;
            #pragma unroll 5
            for (int r = 0; r < 25; r++) {
                float a = aA[g16 * 25 + r];
                float4 v = *(const float4*)(vp + (size_t)r * ED);
                acc.x += a * v.x; acc.y += a * v.y;
                acc.z += a * v.z; acc.w += a * v.w;
            }
            ((float4*)red2)[g16 * 32 + lane] = acc;
            __syncthreads();
            if (tid < 128) {
                float s = 0.f;
                #pragma unroll
                for (int gg = 0; gg < 16; gg++) s += red2[gg * 128 + tid];
                int d = qq * 128 + tid;
                c_out[((size_t)bb * TDEC + t) * ED + d] = s;
                int kk = 80 + d;
                u16 hh, ll; bsplit(s, hh, ll);
                size_t xo = ((size_t)(kk >> 7) * 32 + bb) * ROWE + (kk & 127);
                g_x0h[cu][xo] = hh; g_x0l[cu][xo] = ll;
            }
        }
        grid_sync();
    }
}

// ---------------- prep kernels ----------------
__global__ void k_prep(const float* __restrict__ dec, const float* __restrict__ ck,
                       const float* __restrict__ cb, const float* __restrict__ Wloc) {
    int gid = blockIdx.x * 256 + threadIdx.x;
    int stride = gridDim.x * 256;
    for (int i = gid; i < KER * UN; i += stride) {
        int k = i >> 7, u = i & 127;
        float s = 0.f;
        for (int f = 0; f < FIL; f++) s += ck[k * FIL + f] * Wloc[f * UN + u];
        g_Wc[i] = s;
    }
    for (int i = gid; i < UN; i += stride) {
        float s = 0.f;
        for (int f = 0; f < FIL; f++) s += cb[f] * Wloc[f * UN + i];
        g_locb[i] = s;
    }
    for (int i = gid; i < B * LS; i += stride) { g_c0[i] = 0.f; g_c1[i] = 0.f; }
    for (int i = gid; i < B * TENC; i += stride) g_align[i] = 0.f;
    for (int i = gid; i < B * UN; i += stride) g_pq[i] = 0.f;
    for (int i = gid; i < B; i += stride) g_flag[i] = 0u;
    if (gid == 0) { g_bar_count = 0u; g_bar_gen = 0u; }
    for (int i = gid; i < 2 * NCH0 * CHE; i += stride) {
        int par = i / (NCH0 * CHE), r = i % (NCH0 * CHE);
        int ch = r / CHE, rr = r % CHE;
        int b = rr / ROWE, kk = rr % ROWE;
        float v = 0.f;
        if (par == 0 && ch == 0 && kk < DD) v = dec[(size_t)b * TDEC * DD + kk];
        u16 hh, ll; bsplit(v, hh, ll);
        g_x0h[par][r] = hh; g_x0l[par][r] = ll;
    }
    for (int i = gid; i < 2 * NCH1 * CHE; i += stride) {
        int par = i / (NCH1 * CHE), r = i % (NCH1 * CHE);
        g_x1h[par][r] = 0; g_x1l[par][r] = 0;
    }
    for (size_t i = gid; i < (size_t)B * TDEC * DD; i += stride) {
        u16 hh, ll; bsplit(dec[i], hh, ll);
        g_dech[i] = hh; g_decl[i] = ll;
    }
}

__global__ void k_wt(const float* __restrict__ W0, const float* __restrict__ U0,
                     const float* __restrict__ W1, const float* __restrict__ U1) {
    size_t idx = (size_t)blockIdx.x * 256 + threadIdx.x;
    const size_t total0 = (size_t)128 * NCH0 * CHE;
    const size_t total1 = (size_t)128 * NCH1 * CHE;
    int layer; size_t li;
    const float *W, *U; int ksplit, kreal, nch;
    if (idx < total0) {
        layer = 0; li = idx; W = W0; U = U0; ksplit = DD + ED; kreal = K0REAL; nch = NCH0;
    } else if (idx < total0 + total1) {
        layer = 1; li = idx - total0; W = W1; U = U1; ksplit = LS; kreal = 2 * LS; nch = NCH1;
    } else return;
    int kk = (int)(li % ROWE);
    size_t t1 = li / ROWE;
    int n = (int)(t1 & 31);
    size_t t2 = t1 >> 5;
    int ch = (int)(t2 % nch);
    int cta = (int)(t2 / nch);
    float v = 0.f;
    if (kk < 128) {
        int k = ch * 128 + kk;
        int col = (n >> 3) * 1024 + cta * 8 + (n & 7);
        if (k < ksplit)      v = W[(size_t)k * 4096 + col];
        else if (k < kreal)  v = U[(size_t)(k - ksplit) * 4096 + col];
    }
    u16 hh, ll; bsplit(v, hh, ll);
    if (layer == 0) { g_Wh0[li] = hh; g_Wl0[li] = ll; }
    else            { g_Wh1[li] = hh; g_Wl1[li] = ll; }
}

__global__ void k_keys(const float* __restrict__ values, const float* __restrict__ Wm) {
    int b = blockIdx.x, t0 = blockIdx.y * 50;
    __shared__ float vs[10][ED];
    int u = threadIdx.x;
    for (int g = 0; g < 5; g++) {
        int tb = t0 + g * 10;
        __syncthreads();
        for (int i = u; i < 10 * ED; i += 128) {
            int tt = i >> 9, d = i & 511;
            vs[tt][d] = values[((size_t)b * TENC + tb + tt) * ED + d];
        }
        __syncthreads();
        float acc[10];
        #pragma unroll
        for (int tt = 0; tt < 10; tt++) acc[tt] = 0.f;
        for (int d = 0; d < ED; d++) {
            float w = Wm[d * UN + u];
            #pragma unroll
            for (int tt = 0; tt < 10; tt++) acc[tt] += vs[tt][d] * w;
        }
        #pragma unroll
        for (int tt = 0; tt < 10; tt++)
            g_keys[((size_t)b * TENC + tb + tt) * UN + u] = acc[tt];
    }
}

// ---------------- launch ----------------
extern "C" void kernel_launch(void* const* d_in, const int* in_sizes, int n_in,
                              void* d_out, int out_size) {
    const float* values = (const float*)d_in[0];
    const float* dec    = (const float*)d_in[1];
    const float* Wm     = (const float*)d_in[2];
    const float* Wq     = (const float*)d_in[3];
    const float* convk  = (const float*)d_in[4];
    const float* convb  = (const float*)d_in[5];
    const float* Wloc   = (const float*)d_in[6];
    const float* v_a    = (const float*)d_in[7];
    const float* b_a    = (const float*)d_in[8];
    const float* W0     = (const float*)d_in[9];
    const float* U0     = (const float*)d_in[10];
    const float* b0     = (const float*)d_in[11];
    const float* W1     = (const float*)d_in[12];
    const float* U1     = (const float*)d_in[13];
    const float* b1     = (const float*)d_in[14];

    float* out   = (float*)d_out;
    float* c_out = out;                              // [B, TDEC, ED]
    float* e_out = out + (size_t)B * TDEC * ED;      // [B, TDEC, TENC]

    static int smem_set = 0;
    if (!smem_set) {
        cudaFuncSetAttribute(k_persist, cudaFuncAttributeMaxDynamicSharedMemorySize, SMEM_TOTAL);
        smem_set = 1;
    }

    size_t totalw = (size_t)128 * (NCH0 + NCH1) * CHE;
    k_prep<<<512, 256>>>(dec, convk, convb, Wloc);
    k_wt<<<(unsigned)((totalw + 255) / 256), 256>>>(W0, U0, W1, U1);
    k_keys<<<dim3(B, 8), 128>>>(values, Wm);

    k_persist<<<NCTA, 512, SMEM_TOTAL>>>(values, Wq, v_a, b_a, b0, b1, e_out, c_out);
}

// round 17
// speedup vs baseline: 1.2159x; 1.0792x over previous
#include <cuda_runtime.h>
#include <cuda_bf16.h>
#include <math.h>
#include <stdint.h>

#define NCTA 128
#define B    32
#define TENC 400
#define ED   512
#define TDEC 800
#define DD   80
#define LS   1024
#define UN   128
#define KER  31
#define FIL  32
#define NCH0 13
#define NCH1 16
#define NCHT 29
#define K0REAL 1616
#define ROWE  136              // u16 elems per row (272 B)
#define SROWB 272
#define CHE   (32 * ROWE)      // 4352 elems
#define TILEB 8704
#define STAGEB (4 * TILEB)     // 34816
#define NST   4

// ---- smem offsets (bytes) ----
#define OFF_ZSM   139264
#define OFF_KEYS  156160
#define OFF_WQS   207360
#define OFF_HS    211456
#define OFF_MBAR  212480
#define OFF_AS    212560
#define OFF_SPART 213104
#define OFF_SS    214704
#define OFF_AA    216304
#define OFF_RED   217904
#define OFF_RED2  218032
#define SMEM_TOTAL 226224

typedef unsigned short u16;

// ---------------- device state ----------------
__device__ __align__(16) u16 g_Wh0[128 * NCH0 * CHE];
__device__ __align__(16) u16 g_Wl0[128 * NCH0 * CHE];
__device__ __align__(16) u16 g_Wh1[128 * NCH1 * CHE];
__device__ __align__(16) u16 g_Wl1[128 * NCH1 * CHE];
__device__ __align__(16) u16 g_x0h[2][NCH0 * CHE];
__device__ __align__(16) u16 g_x0l[2][NCH0 * CHE];
__device__ __align__(16) u16 g_x1h[2][NCH1 * CHE];
__device__ __align__(16) u16 g_x1l[2][NCH1 * CHE];
__device__ __align__(16) u16 g_dech[B * TDEC * DD];
__device__ __align__(16) u16 g_decl[B * TDEC * DD];
__device__ __align__(16) float g_keys[B * TENC * UN];
__device__ float g_c0[B * LS];
__device__ float g_c1[B * LS];
__device__ float g_align[B * TENC];
__device__ float g_scores[B * TENC];
__device__ float g_pq[B * UN];
__device__ float g_Wc[KER * UN];
__device__ float g_locb[UN];
__device__ unsigned g_flag[B];
__device__ unsigned g_bar_count;
__device__ volatile unsigned g_bar_gen;

// ---------------- helpers ----------------
__device__ __forceinline__ void bsplit(float v, u16& h, u16& l) {
    __nv_bfloat16 hb = __float2bfloat16(v);
    float rh = __bfloat162float(hb);
    __nv_bfloat16 lb = __float2bfloat16(v - rh);
    h = *(u16*)&hb; l = *(u16*)&lb;
}
__device__ __forceinline__ void bulk(uint32_t dst, const void* src, uint32_t bytes, uint32_t mb) {
    asm volatile("cp.async.bulk.shared::cta.global.mbarrier::complete_tx::bytes [%0], [%1], %2, [%3];"
                 :: "r"(dst), "l"(src), "r"(bytes), "r"(mb) : "memory");
}
__device__ __forceinline__ void mbar_init(uint32_t mb, uint32_t cnt) {
    asm volatile("mbarrier.init.shared.b64 [%0], %1;" :: "r"(mb), "r"(cnt) : "memory");
}
__device__ __forceinline__ void mbar_expect(uint32_t mb, uint32_t bytes) {
    asm volatile("mbarrier.arrive.expect_tx.shared.b64 _, [%0], %1;" :: "r"(mb), "r"(bytes) : "memory");
}
__device__ __forceinline__ void mbar_arrive(uint32_t mb) {
    asm volatile("mbarrier.arrive.shared.b64 _, [%0];" :: "r"(mb) : "memory");
}
__device__ __forceinline__ void mbar_wait(uint32_t mb, uint32_t phase) {
    asm volatile("{\n\t.reg .pred P;\n"
                 "W%=:\n\tmbarrier.try_wait.parity.shared.b64 P, [%0], %1;\n"
                 "\t@P bra D%=;\n\tbra W%=;\nD%=:\n\t}"
                 :: "r"(mb), "r"(phase) : "memory");
}
__device__ __forceinline__ void ldsm4(uint32_t a, uint32_t& r0, uint32_t& r1,
                                      uint32_t& r2, uint32_t& r3) {
    asm volatile("ldmatrix.sync.aligned.m8n8.x4.shared.b16 {%0,%1,%2,%3}, [%4];"
                 : "=r"(r0), "=r"(r1), "=r"(r2), "=r"(r3) : "r"(a));
}
__device__ __forceinline__ void mma16816(float* c, uint32_t a0, uint32_t a1,
                                         uint32_t a2, uint32_t a3,
                                         uint32_t b0, uint32_t b1) {
    asm volatile("mma.sync.aligned.m16n8k16.row.col.f32.bf16.bf16.f32 "
                 "{%0,%1,%2,%3},{%4,%5,%6,%7},{%8,%9},{%0,%1,%2,%3};"
                 : "+f"(c[0]), "+f"(c[1]), "+f"(c[2]), "+f"(c[3])
                 : "r"(a0), "r"(a1), "r"(a2), "r"(a3), "r"(b0), "r"(b1));
}
// fast transcendentals (MUFU-based)
__device__ __forceinline__ float fsig(float x) {
    float e = __expf(-x);
    return __fdividef(1.f, 1.f + e);
}
__device__ __forceinline__ float ftanh(float x) {
    x = fminf(15.f, fmaxf(-15.f, x));
    float e = __expf(2.f * x);
    return __fdividef(e - 1.f, e + 1.f);
}

__device__ __forceinline__ void grid_sync() {
    __threadfence();
    __syncthreads();
    if (threadIdx.x == 0) {
        unsigned gen = g_bar_gen;
        if (atomicAdd(&g_bar_count, 1u) == NCTA - 1) {
            g_bar_count = 0;
            __threadfence();
            g_bar_gen = gen + 1;
        } else {
            while (g_bar_gen == gen) __nanosleep(32);
        }
    }
    __syncthreads();
    __threadfence();
}

// ---------------- issue helpers (producer threads: tid 0 / tid 256) ----------------
__device__ __forceinline__ void issueW(uint32_t smbase, int g,
                                       const u16* Wh, const u16* Wl, size_t chunkIdx) {
    int s = g & 3;
    if (g >= NST) mbar_wait(smbase + OFF_MBAR + 32 + s * 8, (uint32_t)(((g >> 2) - 1) & 1));
    uint32_t buf = smbase + s * STAGEB;
    uint32_t mb  = smbase + OFF_MBAR + s * 8;
    mbar_expect(mb, 2 * TILEB);
    bulk(buf,         Wh + chunkIdx * CHE, TILEB, mb);
    bulk(buf + TILEB, Wl + chunkIdx * CHE, TILEB, mb);
}
__device__ __forceinline__ void issueX(uint32_t smbase, int g,
                                       const u16* Xh, const u16* Xl, int ch) {
    int s = g & 3;
    uint32_t buf = smbase + s * STAGEB;
    uint32_t mb  = smbase + OFF_MBAR + s * 8;
    mbar_expect(mb, 2 * TILEB);
    bulk(buf + 2 * TILEB, Xh + (size_t)ch * CHE, TILEB, mb);
    bulk(buf + 3 * TILEB, Xl + (size_t)ch * CHE, TILEB, mb);
}

// ---------------- chunk MMA (warp covers 16 n-cols x 32 k, two 16-k sub-blocks) ----------------
__device__ __forceinline__ void chunk_mma(uint32_t st, uint32_t aoff, uint32_t boff,
                                          float c[2][2][4]) {
    uint32_t wh = st, wl = st + TILEB, xh = st + 2 * TILEB, xl = st + 3 * TILEB;
    #pragma unroll
    for (int kk = 0; kk < 2; kk++) {
        uint32_t kb = kk * 32;
        uint32_t w0, w1, w2, w3, v0, v1, v2, v3;
        ldsm4(wh + boff + kb, w0, w1, w2, w3);
        ldsm4(wl + boff + kb, v0, v1, v2, v3);
        #pragma unroll
        for (int mt = 0; mt < 2; mt++) {
            uint32_t a0, a1, a2, a3, e0, e1, e2, e3;
            ldsm4(xh + aoff + kb + mt * 16 * SROWB, a0, a1, a2, a3);
            ldsm4(xl + aoff + kb + mt * 16 * SROWB, e0, e1, e2, e3);
            mma16816(c[mt][0], a0, a1, a2, a3, w0, w2);
            mma16816(c[mt][0], a0, a1, a2, a3, v0, v2);
            mma16816(c[mt][0], e0, e1, e2, e3, w0, w2);
            mma16816(c[mt][1], a0, a1, a2, a3, w1, w3);
            mma16816(c[mt][1], a0, a1, a2, a3, v1, v3);
            mma16816(c[mt][1], e0, e1, e2, e3, w1, w3);
        }
    }
}

// group grp consumes chunks ch = grp, grp+2, ... ; its producer is tid (grp ? 256 : 0)
template <int NCH>
__device__ __forceinline__ void gemm_phase(uint32_t smbase, int tid, int lane, int grp,
        int gbase, int cta,
        const u16* Wh, const u16* Wl, const u16* Xh, const u16* Xl,
        uint32_t aoff, uint32_t boff, float c[2][2][4]) {
    int prodTid = grp ? 256 : 0;
    for (int ch = grp; ch < NCH; ch += 2) {
        int g = gbase + ch;
        int s = g & 3;
        mbar_wait(smbase + OFF_MBAR + s * 8, (uint32_t)((g >> 2) & 1));
        chunk_mma(smbase + s * STAGEB, aoff, boff, c);
        if (lane == 0) mbar_arrive(smbase + OFF_MBAR + 32 + s * 8);
        if (tid == prodTid && ch + NST < NCH) {
            issueW(smbase, g + NST, Wh, Wl, (size_t)(cta * NCH + ch + NST));
            issueX(smbase, g + NST, Xh, Xl, ch + NST);
        }
    }
}

// two-pass partial store: group A (grp 0) stores region kw; group B accumulates
__device__ __forceinline__ void zstore(float* zsm, int grp, int kw, int n0, int lane,
                                       float c[2][2][4]) {
    float* zz = zsm + kw * 1056;
    int r = lane >> 2, cp = (lane & 3) * 2;
    if (grp == 0) {
        #pragma unroll
        for (int mt = 0; mt < 2; mt++)
            #pragma unroll
            for (int nn = 0; nn < 2; nn++) {
                int col = n0 + nn * 8 + cp;
                zz[(mt * 16 + r) * 33 + col]         = c[mt][nn][0];
                zz[(mt * 16 + r) * 33 + col + 1]     = c[mt][nn][1];
                zz[(mt * 16 + 8 + r) * 33 + col]     = c[mt][nn][2];
                zz[(mt * 16 + 8 + r) * 33 + col + 1] = c[mt][nn][3];
            }
    }
    __syncthreads();
    if (grp == 1) {
        #pragma unroll
        for (int mt = 0; mt < 2; mt++)
            #pragma unroll
            for (int nn = 0; nn < 2; nn++) {
                int col = n0 + nn * 8 + cp;
                zz[(mt * 16 + r) * 33 + col]         += c[mt][nn][0];
                zz[(mt * 16 + r) * 33 + col + 1]     += c[mt][nn][1];
                zz[(mt * 16 + 8 + r) * 33 + col]     += c[mt][nn][2];
                zz[(mt * 16 + 8 + r) * 33 + col + 1] += c[mt][nn][3];
            }
    }
    __syncthreads();
}

// ---------------- persistent kernel ----------------
__global__ void __launch_bounds__(512, 1) k_persist(
        const float* __restrict__ values, const float* __restrict__ Wq,
        const float* __restrict__ v_a, const float* __restrict__ b_a,
        const float* __restrict__ bias0, const float* __restrict__ bias1,
        float* __restrict__ e_out, float* __restrict__ c_out) {
    extern __shared__ char sm[];
    uint32_t smbase = (uint32_t)__cvta_generic_to_shared(sm);
    int cta = blockIdx.x, tid = threadIdx.x;
    int lane = tid & 31, warp = tid >> 5;
    int grp = warp >> 3;                 // 0: even chunks, 1: odd chunks
    int idx = warp & 7;
    int nt = idx & 1, kw = idx >> 1, n0 = nt * 16;
    uint32_t aoff = (uint32_t)((lane & 15) * SROWB + (lane >> 4) * 16 + kw * 64);
    uint32_t boff = (uint32_t)((n0 + (lane & 15)) * SROWB + (lane >> 4) * 16 + kw * 64);
    int bb = cta >> 2, qq = cta & 3;

    float* zsm   = (float*)(sm + OFF_ZSM);
    float* keysS = (float*)(sm + OFF_KEYS);
    float* wqs   = (float*)(sm + OFF_WQS);
    float* hs    = (float*)(sm + OFF_HS);
    float* aS    = (float*)(sm + OFF_AS);
    float* spart = (float*)(sm + OFF_SPART);
    float* sS    = (float*)(sm + OFF_SS);
    float* aA    = (float*)(sm + OFF_AA);
    float* red   = (float*)(sm + OFF_RED);
    float* red2  = (float*)(sm + OFF_RED2);

    if (tid == 0) {
        #pragma unroll
        for (int s = 0; s < NST; s++) {
            mbar_init(smbase + OFF_MBAR + s * 8, 2);        // full (2 expect_tx arrivals)
            mbar_init(smbase + OFF_MBAR + 32 + s * 8, 8);   // empty (8 warps of owning group)
        }
        mbar_init(smbase + OFF_MBAR + 64, 1);               // keys
    }
    // Wq slice (8 rows x 128) into smem
    for (int i = tid; i < 8 * 128; i += 512)
        wqs[i] = Wq[(size_t)(cta * 8 + (i >> 7)) * UN + (i & 127)];
    __syncthreads();
    if (tid == 0) {
        uint32_t km = smbase + OFF_MBAR + 64;
        mbar_expect(km, 100 * UN * 4);
        bulk(smbase + OFF_KEYS, g_keys + ((size_t)bb * TENC + qq * 100) * UN, 100 * UN * 4, km);
        issueW(smbase, 0, g_Wh0, g_Wl0, (size_t)(cta * NCH0 + 0));
        issueX(smbase, 0, g_x0h[0], g_x0l[0], 0);
        issueW(smbase, 2, g_Wh0, g_Wl0, (size_t)(cta * NCH0 + 2));
        issueX(smbase, 2, g_x0h[0], g_x0l[0], 2);
    }
    if (tid == 256) {
        issueW(smbase, 1, g_Wh0, g_Wl0, (size_t)(cta * NCH0 + 1));
        issueX(smbase, 1, g_x0h[0], g_x0l[0], 1);
        issueW(smbase, 3, g_Wh0, g_Wl0, (size_t)(cta * NCH0 + 3));
        issueX(smbase, 3, g_x0h[0], g_x0l[0], 3);
    }
    mbar_wait(smbase + OFF_MBAR + 64, 0);
    __syncthreads();

    for (int t = 0; t < TDEC; t++) {
        int pr = t & 1, cu = pr ^ 1;
        int g0 = NCHT * t, g1 = g0 + NCH0;

        // X for L0 chunks 0..3 (W pre-issued in previous L1 epilogue; t=0 in prologue)
        if (t > 0) {
            if (tid == 0) {
                issueX(smbase, g0 + 0, g_x0h[pr], g_x0l[pr], 0);
                issueX(smbase, g0 + 2, g_x0h[pr], g_x0l[pr], 2);
            }
            if (tid == 256) {
                issueX(smbase, g0 + 1, g_x0h[pr], g_x0l[pr], 1);
                issueX(smbase, g0 + 3, g_x0h[pr], g_x0l[pr], 3);
            }
        }
        float c[2][2][4];
        #pragma unroll
        for (int a = 0; a < 2; a++)
            #pragma unroll
            for (int bq = 0; bq < 2; bq++)
                #pragma unroll
                for (int j = 0; j < 4; j++) c[a][bq][j] = 0.f;
        gemm_phase<NCH0>(smbase, tid, lane, grp, g0, cta, g_Wh0, g_Wl0, g_x0h[pr], g_x0l[pr],
                         aoff, boff, c);
        // ---- L0 epilogue ----
        zstore(zsm, grp, kw, n0, lane, c);
        if (tid == 0) {   // pre-issue W for L1 chunks 0,2
            issueW(smbase, g1 + 0, g_Wh1, g_Wl1, (size_t)(cta * NCH1 + 0));
            issueW(smbase, g1 + 2, g_Wh1, g_Wl1, (size_t)(cta * NCH1 + 2));
        }
        if (tid == 256) { // pre-issue W for L1 chunks 1,3
            issueW(smbase, g1 + 1, g_Wh1, g_Wl1, (size_t)(cta * NCH1 + 1));
            issueW(smbase, g1 + 3, g_Wh1, g_Wl1, (size_t)(cta * NCH1 + 3));
        }
        if (tid < 256) {
            int j = tid >> 5, b = tid & 31;
            int u = cta * 8 + j;
            float z[4];
            #pragma unroll
            for (int g4 = 0; g4 < 4; g4++) {
                float v = bias0[g4 * 1024 + u];
                #pragma unroll
                for (int q = 0; q < 4; q++) v += zsm[q * 1056 + b * 33 + g4 * 8 + j];
                z[g4] = v;
            }
            float co = g_c0[b * LS + u];
            float cn = fsig(z[1]) * co + fsig(z[0]) * ftanh(z[2]);
            g_c0[b * LS + u] = cn;
            float h = fsig(z[3]) * ftanh(cn);
            u16 hh, ll; bsplit(h, hh, ll);
            size_t o1 = ((size_t)(u >> 7) * 32 + b) * ROWE + (u & 127);          // x1 k=u
            g_x1h[pr][o1] = hh; g_x1l[pr][o1] = ll;
            int k0 = 592 + u;
            size_t o0 = ((size_t)(k0 >> 7) * 32 + b) * ROWE + (k0 & 127);        // x0 next
            g_x0h[cu][o0] = hh; g_x0l[cu][o0] = ll;
        }
        grid_sync();

        if (tid == 0) {
            issueX(smbase, g1 + 0, g_x1h[pr], g_x1l[pr], 0);
            issueX(smbase, g1 + 2, g_x1h[pr], g_x1l[pr], 2);
        }
        if (tid == 256) {
            issueX(smbase, g1 + 1, g_x1h[pr], g_x1l[pr], 1);
            issueX(smbase, g1 + 3, g_x1h[pr], g_x1l[pr], 3);
        }
        #pragma unroll
        for (int a = 0; a < 2; a++)
            #pragma unroll
            for (int bq = 0; bq < 2; bq++)
                #pragma unroll
                for (int j = 0; j < 4; j++) c[a][bq][j] = 0.f;
        gemm_phase<NCH1>(smbase, tid, lane, grp, g1, cta, g_Wh1, g_Wl1, g_x1h[pr], g_x1l[pr],
                         aoff, boff, c);
        // ---- L1 epilogue (+ fused pq partial) ----
        zstore(zsm, grp, kw, n0, lane, c);
        if (t + 1 < TDEC) {   // pre-issue W for next step's L0
            if (tid == 0) {
                issueW(smbase, NCHT * (t + 1) + 0, g_Wh0, g_Wl0, (size_t)(cta * NCH0 + 0));
                issueW(smbase, NCHT * (t + 1) + 2, g_Wh0, g_Wl0, (size_t)(cta * NCH0 + 2));
            }
            if (tid == 256) {
                issueW(smbase, NCHT * (t + 1) + 1, g_Wh0, g_Wl0, (size_t)(cta * NCH0 + 1));
                issueW(smbase, NCHT * (t + 1) + 3, g_Wh0, g_Wl0, (size_t)(cta * NCH0 + 3));
            }
        }
        if (tid < 256) {
            int j = tid >> 5, b = tid & 31;
            int u = cta * 8 + j;
            float z[4];
            #pragma unroll
            for (int g4 = 0; g4 < 4; g4++) {
                float v = bias1[g4 * 1024 + u];
                #pragma unroll
                for (int q = 0; q < 4; q++) v += zsm[q * 1056 + b * 33 + g4 * 8 + j];
                z[g4] = v;
            }
            float co = g_c1[b * LS + u];
            float cn = fsig(z[1]) * co + fsig(z[0]) * ftanh(z[2]);
            g_c1[b * LS + u] = cn;
            float h = fsig(z[3]) * ftanh(cn);
            u16 hh, ll; bsplit(h, hh, ll);
            int k1 = 1024 + u;
            size_t o1 = ((size_t)(k1 >> 7) * 32 + b) * ROWE + (k1 & 127);
            g_x1h[cu][o1] = hh; g_x1l[cu][o1] = ll;
            hs[j * 32 + b] = h;
        }
        __syncthreads();
        // pq partial: rank-8 update, RED.ADD to g_pq
        {
            int b = tid >> 4, u0 = (tid & 15) * 8;
            float acc[8] = {0.f, 0.f, 0.f, 0.f, 0.f, 0.f, 0.f, 0.f};
            #pragma unroll
            for (int jj = 0; jj < 8; jj++) {
                float h = hs[jj * 32 + b];
                #pragma unroll
                for (int q = 0; q < 8; q++) acc[q] += h * wqs[jj * 128 + u0 + q];
            }
            #pragma unroll
            for (int q = 0; q < 8; q++) atomicAdd(&g_pq[b * UN + u0 + q], acc[q]);
        }
        grid_sync();

        // ---- P3: location conv + scores (keys & Wc smem/reg resident) ----
        {
            int t0 = qq * 100;
            int u = tid & 127, q4 = tid >> 7;
            for (int i = tid; i < 130; i += 512) {
                int tg = t0 - 15 + i;
                aS[i] = (tg >= 0 && tg < TENC) ? __ldcg(&g_align[bb * TENC + tg]) : 0.f;
            }
            float pqu = __ldg(&b_a[u]) + __ldg(&g_locb[u]) + __ldcg(&g_pq[bb * UN + u]);
            float vau = __ldg(&v_a[u]);
            float wc[KER];
            #pragma unroll
            for (int k = 0; k < KER; k++) wc[k] = __ldg(&g_Wc[k * UN + u]);
            __syncthreads();
            int wq = warp & 3;
            for (int tt = 0; tt < 25; tt++) {
                int tl = q4 * 25 + tt;
                float s = keysS[tl * 128 + u] + pqu;
                #pragma unroll
                for (int k = 0; k < KER; k++) s += aS[tl + k] * wc[k];
                float r = vau * ftanh(s);
                #pragma unroll
                for (int o = 16; o; o >>= 1) r += __shfl_xor_sync(0xffffffffu, r, o);
                if (lane == 0) spart[tl * 4 + wq] = r;
            }
            __syncthreads();
            if (tid < 100)
                g_scores[bb * TENC + t0 + tid] =
                    spart[tid * 4] + spart[tid * 4 + 1] + spart[tid * 4 + 2] + spart[tid * 4 + 3];
            __threadfence();
            __syncthreads();
            if (tid == 0) atomicAdd(&g_flag[bb], 1u);
        }

        // ---- P4: softmax + outputs + context slice ----
        {
            if (tid == 0) {
                unsigned tg = 4u * (unsigned)(t + 1);
                while (*((volatile unsigned*)&g_flag[bb]) < tg) __nanosleep(32);
            }
            __syncthreads();
            __threadfence();
            float lm = -1e30f;
            if (tid < TENC) { lm = __ldcg(&g_scores[bb * TENC + tid]); sS[tid] = lm; }
            #pragma unroll
            for (int o = 16; o; o >>= 1) lm = fmaxf(lm, __shfl_xor_sync(0xffffffffu, lm, o));
            if (lane == 0) red[warp] = lm;
            __syncthreads();
            float m = red[0];
            #pragma unroll
            for (int w = 1; w < 16; w++) m = fmaxf(m, red[w]);
            float ex = (tid < TENC) ? __expf(sS[tid] - m) : 0.f;
            float ls = ex;
            #pragma unroll
            for (int o = 16; o; o >>= 1) ls += __shfl_xor_sync(0xffffffffu, ls, o);
            if (lane == 0) red[16 + warp] = ls;
            __syncthreads();
            float S = 0.f;
            #pragma unroll
            for (int w = 0; w < 16; w++) S += red[16 + w];
            float inv = __fdividef(1.f, S);
            if (tid < TENC) aA[tid] = ex * inv;
            __syncthreads();
            if (qq == 0 && tid < TENC) {
                float a = aA[tid];
                e_out[((size_t)bb * TDEC + t) * TENC + tid] = a;
                float al = __ldcg(&g_align[bb * TENC + tid]) + a;
                __stcg(&g_align[bb * TENC + tid], al);
            }
            // dec prefetch for next step (chunk 0, row bb, k = 0..79)
            if (qq == 1 && t + 1 < TDEC && tid < DD) {
                size_t sidx = ((size_t)bb * TDEC + (t + 1)) * DD + tid;
                size_t xo = (size_t)bb * ROWE + tid;
                g_x0h[cu][xo] = g_dech[sidx];
                g_x0l[cu][xo] = g_decl[sidx];
            }
            if (qq == 3 && tid < UN) __stcg(&g_pq[bb * UN + tid], 0.f);
            // context slice [qq*128, +128): 16 warps x 25 rows
            int g16 = tid >> 5;
            float4 acc = make_float4(0.f, 0.f, 0.f, 0.f);
            const float* vp = values + ((size_t)bb * TENC + g16 * 25) * ED + qq * 128 + lane * 4;
            #pragma unroll 5
            for (int r = 0; r < 25; r++) {
                float a = aA[g16 * 25 + r];
                float4 v = *(const float4*)(vp + (size_t)r * ED);
                acc.x += a * v.x; acc.y += a * v.y;
                acc.z += a * v.z; acc.w += a * v.w;
            }
            ((float4*)red2)[g16 * 32 + lane] = acc;
            __syncthreads();
            if (tid < 128) {
                float s = 0.f;
                #pragma unroll
                for (int gg = 0; gg < 16; gg++) s += red2[gg * 128 + tid];
                int d = qq * 128 + tid;
                c_out[((size_t)bb * TDEC + t) * ED + d] = s;
                int kk = 80 + d;
                u16 hh, ll; bsplit(s, hh, ll);
                size_t xo = ((size_t)(kk >> 7) * 32 + bb) * ROWE + (kk & 127);
                g_x0h[cu][xo] = hh; g_x0l[cu][xo] = ll;
            }
        }
        grid_sync();
    }
}

// ---------------- prep kernels ----------------
__global__ void k_prep(const float* __restrict__ dec, const float* __restrict__ ck,
                       const float* __restrict__ cb, const float* __restrict__ Wloc) {
    int gid = blockIdx.x * 256 + threadIdx.x;
    int stride = gridDim.x * 256;
    for (int i = gid; i < KER * UN; i += stride) {
        int k = i >> 7, u = i & 127;
        float s = 0.f;
        for (int f = 0; f < FIL; f++) s += ck[k * FIL + f] * Wloc[f * UN + u];
        g_Wc[i] = s;
    }
    for (int i = gid; i < UN; i += stride) {
        float s = 0.f;
        for (int f = 0; f < FIL; f++) s += cb[f] * Wloc[f * UN + i];
        g_locb[i] = s;
    }
    for (int i = gid; i < B * LS; i += stride) { g_c0[i] = 0.f; g_c1[i] = 0.f; }
    for (int i = gid; i < B * TENC; i += stride) g_align[i] = 0.f;
    for (int i = gid; i < B * UN; i += stride) g_pq[i] = 0.f;
    for (int i = gid; i < B; i += stride) g_flag[i] = 0u;
    if (gid == 0) { g_bar_count = 0u; g_bar_gen = 0u; }
    for (int i = gid; i < 2 * NCH0 * CHE; i += stride) {
        int par = i / (NCH0 * CHE), r = i % (NCH0 * CHE);
        int ch = r / CHE, rr = r % CHE;
        int b = rr / ROWE, kk = rr % ROWE;
        float v = 0.f;
        if (par == 0 && ch == 0 && kk < DD) v = dec[(size_t)b * TDEC * DD + kk];
        u16 hh, ll; bsplit(v, hh, ll);
        g_x0h[par][r] = hh; g_x0l[par][r] = ll;
    }
    for (int i = gid; i < 2 * NCH1 * CHE; i += stride) {
        int par = i / (NCH1 * CHE), r = i % (NCH1 * CHE);
        g_x1h[par][r] = 0; g_x1l[par][r] = 0;
    }
    for (size_t i = gid; i < (size_t)B * TDEC * DD; i += stride) {
        u16 hh, ll; bsplit(dec[i], hh, ll);
        g_dech[i] = hh; g_decl[i] = ll;
    }
}

__global__ void k_wt(const float* __restrict__ W0, const float* __restrict__ U0,
                     const float* __restrict__ W1, const float* __restrict__ U1) {
    size_t idx = (size_t)blockIdx.x * 256 + threadIdx.x;
    const size_t total0 = (size_t)128 * NCH0 * CHE;
    const size_t total1 = (size_t)128 * NCH1 * CHE;
    int layer; size_t li;
    const float *W, *U; int ksplit, kreal, nch;
    if (idx < total0) {
        layer = 0; li = idx; W = W0; U = U0; ksplit = DD + ED; kreal = K0REAL; nch = NCH0;
    } else if (idx < total0 + total1) {
        layer = 1; li = idx - total0; W = W1; U = U1; ksplit = LS; kreal = 2 * LS; nch = NCH1;
    } else return;
    int kk = (int)(li % ROWE);
    size_t t1 = li / ROWE;
    int n = (int)(t1 & 31);
    size_t t2 = t1 >> 5;
    int ch = (int)(t2 % nch);
    int cta = (int)(t2 / nch);
    float v = 0.f;
    if (kk < 128) {
        int k = ch * 128 + kk;
        int col = (n >> 3) * 1024 + cta * 8 + (n & 7);
        if (k < ksplit)      v = W[(size_t)k * 4096 + col];
        else if (k < kreal)  v = U[(size_t)(k - ksplit) * 4096 + col];
    }
    u16 hh, ll; bsplit(v, hh, ll);
    if (layer == 0) { g_Wh0[li] = hh; g_Wl0[li] = ll; }
    else            { g_Wh1[li] = hh; g_Wl1[li] = ll; }
}

__global__ void k_keys(const float* __restrict__ values, const float* __restrict__ Wm) {
    int b = blockIdx.x, t0 = blockIdx.y * 50;
    __shared__ float vs[10][ED];
    int u = threadIdx.x;
    for (int g = 0; g < 5; g++) {
        int tb = t0 + g * 10;
        __syncthreads();
        for (int i = u; i < 10 * ED; i += 128) {
            int tt = i >> 9, d = i & 511;
            vs[tt][d] = values[((size_t)b * TENC + tb + tt) * ED + d];
        }
        __syncthreads();
        float acc[10];
        #pragma unroll
        for (int tt = 0; tt < 10; tt++) acc[tt] = 0.f;
        for (int d = 0; d < ED; d++) {
            float w = Wm[d * UN + u];
            #pragma unroll
            for (int tt = 0; tt < 10; tt++) acc[tt] += vs[tt][d] * w;
        }
        #pragma unroll
        for (int tt = 0; tt < 10; tt++)
            g_keys[((size_t)b * TENC + tb + tt) * UN + u] = acc[tt];
    }
}

// ---------------- launch ----------------
extern "C" void kernel_launch(void* const* d_in, const int* in_sizes, int n_in,
                              void* d_out, int out_size) {
    const float* values = (const float*)d_in[0];
    const float* dec    = (const float*)d_in[1];
    const float* Wm     = (const float*)d_in[2];
    const float* Wq     = (const float*)d_in[3];
    const float* convk  = (const float*)d_in[4];
    const float* convb  = (const float*)d_in[5];
    const float* Wloc   = (const float*)d_in[6];
    const float* v_a    = (const float*)d_in[7];
    const float* b_a    = (const float*)d_in[8];
    const float* W0     = (const float*)d_in[9];
    const float* U0     = (const float*)d_in[10];
    const float* b0     = (const float*)d_in[11];
    const float* W1     = (const float*)d_in[12];
    const float* U1     = (const float*)d_in[13];
    const float* b1     = (const float*)d_in[14];

    float* out   = (float*)d_out;
    float* c_out = out;                              // [B, TDEC, ED]
    float* e_out = out + (size_t)B * TDEC * ED;      // [B, TDEC, TENC]

    static int smem_set = 0;
    if (!smem_set) {
        cudaFuncSetAttribute(k_persist, cudaFuncAttributeMaxDynamicSharedMemorySize, SMEM_TOTAL);
        smem_set = 1;
    }

    size_t totalw = (size_t)128 * (NCH0 + NCH1) * CHE;
    k_prep<<<512, 256>>>(dec, convk, convb, Wloc);
    k_wt<<<(unsigned)((totalw + 255) / 256), 256>>>(W0, U0, W1, U1);
    k_keys<<<dim3(B, 8), 128>>>(values, Wm);

    k_persist<<<NCTA, 512, SMEM_TOTAL>>>(values, Wq, v_a, b_a, b0, b1, e_out, c_out);
}